// round 13
// baseline (speedup 1.0000x reference)
#include <cuda_runtime.h>
#include <cuda_bf16.h>
#include <cstdint>
#include <math.h>

// ---------------- problem constants ----------------
#define D_MODEL 1024
#define D_FF    4096
#define NB      2
#define SEQ     2048
#define NH      16
#define DK      64
#define M_TOT   (NB*SEQ)          // 4096 rows

enum { MODE_BIAS = 0, MODE_QKV = 1, MODE_RELU = 2, MODE_RES = 3 };

// ---------------- scratch (static device arrays; no allocations) ----------------
__device__ float g_q  [M_TOT * D_MODEL];   // [B,H,S,DK]
__device__ float g_k  [M_TOT * D_MODEL];
__device__ float g_v  [M_TOT * D_MODEL];
__device__ float g_ctx[M_TOT * D_MODEL];   // [B,S,D]
__device__ float g_t  [M_TOT * D_MODEL];   // residual sums
__device__ float g_x  [M_TOT * D_MODEL];   // LN1 output
__device__ float g_h  [M_TOT * D_FF];      // FFN hidden
// bf16 split operand buffers (reused sequentially by every GEMM)
__device__ __nv_bfloat16 g_abuf[(size_t)M_TOT * 3 * D_FF];    // up to 4096 x 12288
__device__ __nv_bfloat16 g_wbuf[(size_t)D_FF * 3 * D_MODEL];  // up to 4096 x 3072

// ================= PTX helpers (baseline ISA only: sm_80/90 features) =================
__device__ __forceinline__ uint32_t smem_u32(const void* p) {
    uint32_t a;
    asm("{ .reg .u64 t; cvta.to.shared.u64 t, %1; cvt.u32.u64 %0, t; }" : "=r"(a) : "l"(p));
    return a;
}
__device__ __forceinline__ void cp_async16(uint32_t sdst, const void* gsrc) {
    asm volatile("cp.async.cg.shared.global [%0], [%1], 16;" :: "r"(sdst), "l"(gsrc));
}
#define CP_COMMIT() asm volatile("cp.async.commit_group;" ::: "memory")
#define CP_WAIT2()  asm volatile("cp.async.wait_group 2;" ::: "memory")

#define SMEM_SWIZZLE_128B(off) ((off) ^ (((off) >> 3) & 0x70))

#define LDSM_X4(r, addr)                                                        \
    asm volatile("ldmatrix.sync.aligned.m8n8.x4.shared.b16 {%0,%1,%2,%3}, [%4];" \
                 : "=r"((r)[0]), "=r"((r)[1]), "=r"((r)[2]), "=r"((r)[3])        \
                 : "r"(addr))

__device__ __forceinline__ void mma_bf16(float* c, const uint32_t* a,
                                         uint32_t b0, uint32_t b1) {
    asm volatile("mma.sync.aligned.m16n8k16.row.col.f32.bf16.bf16.f32 "
                 "{%0,%1,%2,%3}, {%4,%5,%6,%7}, {%8,%9}, {%0,%1,%2,%3};"
                 : "+f"(c[0]), "+f"(c[1]), "+f"(c[2]), "+f"(c[3])
                 : "r"(a[0]), "r"(a[1]), "r"(a[2]), "r"(a[3]), "r"(b0), "r"(b1));
}

// ================= split-precision conversion kernels =================
// A' row = [A_hi | A_lo | A_hi]  (M x 3K), bf16
__global__ __launch_bounds__(256)
void act_split_kernel(const float* __restrict__ X, __nv_bfloat16* __restrict__ Y,
                      int K, int total4)
{
    int i = blockIdx.x * 256 + threadIdx.x;
    if (i >= total4) return;
    int idx = i << 2;
    float4 v = *(const float4*)&X[idx];
    int m = idx / K, k = idx - m * K;
    __nv_bfloat16 hi4[4], lo4[4];
    hi4[0] = __float2bfloat16(v.x); lo4[0] = __float2bfloat16(v.x - __bfloat162float(hi4[0]));
    hi4[1] = __float2bfloat16(v.y); lo4[1] = __float2bfloat16(v.y - __bfloat162float(hi4[1]));
    hi4[2] = __float2bfloat16(v.z); lo4[2] = __float2bfloat16(v.z - __bfloat162float(hi4[2]));
    hi4[3] = __float2bfloat16(v.w); lo4[3] = __float2bfloat16(v.w - __bfloat162float(hi4[3]));
    size_t base = (size_t)m * 3 * K + k;
    *(uint2*)&Y[base]         = *(uint2*)hi4;
    *(uint2*)&Y[base + K]     = *(uint2*)lo4;
    *(uint2*)&Y[base + 2 * K] = *(uint2*)hi4;
}

// W [K,N] fp32 -> Y [N,3K] bf16 transposed: row = [B_hi | B_hi | B_lo]
__global__ __launch_bounds__(256)
void wt_split_kernel(const float* __restrict__ W, __nv_bfloat16* __restrict__ Y,
                     int K, int N)
{
    __shared__ float tile[32][33];
    const int tx = threadIdx.x & 31, ty = threadIdx.x >> 5;   // ty 0..7
    const int k0 = blockIdx.x * 32, n0 = blockIdx.y * 32;
    #pragma unroll
    for (int u = 0; u < 4; u++)
        tile[ty + 8 * u][tx] = W[(size_t)(k0 + ty + 8 * u) * N + n0 + tx];
    __syncthreads();
    #pragma unroll
    for (int u = 0; u < 4; u++) {
        const int n = n0 + ty + 8 * u;
        const float x = tile[tx][ty + 8 * u];
        const __nv_bfloat16 h = __float2bfloat16(x);
        const __nv_bfloat16 l = __float2bfloat16(x - __bfloat162float(h));
        const size_t base = (size_t)n * 3 * K + (k0 + tx);
        Y[base]         = h;
        Y[base + K]     = h;
        Y[base + 2 * K] = l;
    }
}

// ================= HMMA bf16 GEMM: C[M,N] = A'[M,Kp] @ B'[N,Kp]^T =================
// 128x128 CTA tile, 8 warps (2x4 -> 64x32 per warp), K-chunk = 64 bf16
// (128 B per row, SW128 swizzle), 3-stage cp.async pipeline.
#define GS          3
#define TILE_AB     16384                 // 128 rows x 128 bytes
#define STAGE_BYTES (2 * TILE_AB)
#define GEMM_SMEM   (GS * STAGE_BYTES)    // 98304 B

template<int MODE>
__global__ __launch_bounds__(256, 2)
void tc_gemm(const __nv_bfloat16* __restrict__ A, const __nv_bfloat16* __restrict__ Bw,
             const float* __restrict__ bias, const float* __restrict__ Res,
             float* __restrict__ C, int N, int Kp)
{
    extern __shared__ __align__(1024) char smem[];
    const uint32_t tiles = smem_u32(smem);
    const int t    = threadIdx.x;
    const int lane = t & 31;
    const int wid  = t >> 5;
    const int wm   = wid >> 2;          // 0..1  (64 rows)
    const int wn   = wid & 3;           // 0..3  (32 cols)
    const int n0   = blockIdx.x * 128;
    const int m0   = blockIdx.y * 128;

#define LOAD_CHUNK(CH, ST) do {                                                        \
    const size_t kb = (size_t)(CH) * 128;                                              \
    const uint32_t aB = tiles + (ST) * STAGE_BYTES;                                    \
    const uint32_t bB = aB + TILE_AB;                                                  \
    _Pragma("unroll")                                                                  \
    for (int u = 0; u < 4; u++) {                                                      \
        const int idx = t + 256 * u;                                                   \
        const int row = idx >> 3;                                                      \
        const int c8  = (idx & 7) << 4;                                                \
        const uint32_t sw = SMEM_SWIZZLE_128B((uint32_t)(row * 128 + c8));             \
        cp_async16(aB + sw, (const char*)A  + (size_t)(m0 + row) * (size_t)Kp * 2 + kb + c8); \
        cp_async16(bB + sw, (const char*)Bw + (size_t)(n0 + row) * (size_t)Kp * 2 + kb + c8); \
    }                                                                                  \
    CP_COMMIT();                                                                       \
} while (0)

    const int nch = Kp >> 6;
    #pragma unroll
    for (int p = 0; p < GS; p++) LOAD_CHUNK(p, p);

    float acc[4][4][4];
    #pragma unroll
    for (int mt = 0; mt < 4; mt++)
        #pragma unroll
        for (int nt = 0; nt < 4; nt++)
            #pragma unroll
            for (int r = 0; r < 4; r++) acc[mt][nt][r] = 0.f;

    // ldmatrix lane address components (constant across chunks)
    const int a_row = wm * 64 + (lane & 15);           // + mt*16
    const int a_kb  = (lane >> 4) << 4;                // + ks*32  (bytes)
    const int b_row = wn * 32 + (lane & 7) + ((lane >> 4) << 3);   // + nt2*16
    const int b_kb  = ((lane >> 3) & 1) << 4;          // + ks*32  (bytes)

    #pragma unroll 1
    for (int c = 0; c < nch; c++) {
        const int st = c % GS;
        CP_WAIT2();
        __syncthreads();

        const uint32_t aB = tiles + st * STAGE_BYTES;
        const uint32_t bB = aB + TILE_AB;

        #pragma unroll
        for (int ks = 0; ks < 4; ks++) {
            uint32_t af[4][4];
            #pragma unroll
            for (int mt = 0; mt < 4; mt++) {
                const uint32_t off = SMEM_SWIZZLE_128B(
                    (uint32_t)((a_row + mt * 16) * 128 + ks * 32 + a_kb));
                LDSM_X4(af[mt], aB + off);
            }
            uint32_t bf[2][4];
            #pragma unroll
            for (int nt2 = 0; nt2 < 2; nt2++) {
                const uint32_t off = SMEM_SWIZZLE_128B(
                    (uint32_t)((b_row + nt2 * 16) * 128 + ks * 32 + b_kb));
                LDSM_X4(bf[nt2], bB + off);
            }
            #pragma unroll
            for (int mt = 0; mt < 4; mt++)
                #pragma unroll
                for (int nt = 0; nt < 4; nt++)
                    mma_bf16(acc[mt][nt], af[mt],
                             bf[nt >> 1][(nt & 1) * 2], bf[nt >> 1][(nt & 1) * 2 + 1]);
        }

        __syncthreads();
        if (c + GS < nch) LOAD_CHUNK(c + GS, st);
        else              CP_COMMIT();   // keep per-thread group count invariant
    }
#undef LOAD_CHUNK

    // ---------------- epilogue ----------------
    const int qr = lane >> 2;          // 0..7
    const int qc = (lane & 3) << 1;    // 0,2,4,6
    #pragma unroll
    for (int mt = 0; mt < 4; mt++) {
        #pragma unroll
        for (int nt = 0; nt < 4; nt++) {
            const int col = n0 + wn * 32 + nt * 8 + qc;
            const float2 bv = *(const float2*)&bias[col];
            #pragma unroll
            for (int half = 0; half < 2; half++) {
                const int row = m0 + wm * 64 + mt * 16 + qr + half * 8;
                float2 r;
                r.x = acc[mt][nt][half * 2 + 0] + bv.x;
                r.y = acc[mt][nt][half * 2 + 1] + bv.y;
                if (MODE == MODE_RELU) {
                    r.x = fmaxf(r.x, 0.f); r.y = fmaxf(r.y, 0.f);
                }
                if (MODE == MODE_RES) {
                    float2 rv = *(const float2*)&Res[(size_t)row * N + col];
                    r.x += rv.x; r.y += rv.y;
                }
                if (MODE == MODE_QKV) {
                    const int h = col >> 6, d = col & 63;
                    const int bb = row >> 11, ss = row & 2047;
                    *(float2*)&C[((size_t)(bb * NH + h) * SEQ + ss) * DK + d] = r;
                } else {
                    *(float2*)&C[(size_t)row * N + col] = r;
                }
            }
        }
    }
}

// ---------------- flash attention (causal, strict j < i; row 0 zeroed) ----------------
#define AST 68
#define ATTN_SMEM (4 * 64 * AST * (int)sizeof(float))

__device__ __forceinline__ float rmax16(float v) {
    #pragma unroll
    for (int o = 8; o; o >>= 1) v = fmaxf(v, __shfl_xor_sync(0xffffffffu, v, o));
    return v;
}
__device__ __forceinline__ float rsum16(float v) {
    #pragma unroll
    for (int o = 8; o; o >>= 1) v += __shfl_xor_sync(0xffffffffu, v, o);
    return v;
}

__global__ __launch_bounds__(256, 2)
void attn_kernel(const float* __restrict__ Q, const float* __restrict__ Kg,
                 const float* __restrict__ Vg, float* __restrict__ ctx)
{
    extern __shared__ float sm[];
    float* Qs  = sm;
    float* KsT = sm + 64 * AST;
    float* Vs  = sm + 2 * 64 * AST;
    float* Ps  = sm + 3 * 64 * AST;

    const int t  = threadIdx.x;
    const int tr = t >> 4;
    const int tc = t & 15;
    const int qt = gridDim.x - 1 - blockIdx.x;   // longest tiles first
    const int bh = blockIdx.y;
    const int q0 = qt * 64;

    const float* Qb = Q  + (size_t)bh * SEQ * DK;
    const float* Kb = Kg + (size_t)bh * SEQ * DK;
    const float* Vb = Vg + (size_t)bh * SEQ * DK;

    {
        const int r  = t >> 2;
        const int db = (t & 3) * 16;
        #pragma unroll
        for (int u = 0; u < 4; u++) {
            float4 v = *(const float4*)&Qb[(size_t)(q0 + r) * DK + db + 4 * u];
            v.x *= 0.125f; v.y *= 0.125f; v.z *= 0.125f; v.w *= 0.125f;
            *(float4*)&Qs[r * AST + db + 4 * u] = v;
        }
    }

    float o[4][4];
    float m[4], l[4];
    #pragma unroll
    for (int i = 0; i < 4; i++) {
        m[i] = -1e30f; l[i] = 0.f;
        #pragma unroll
        for (int j = 0; j < 4; j++) o[i][j] = 0.f;
    }

    for (int kt = 0; kt <= qt; kt++) {
        {
            const int r  = t >> 2;
            const int db = (t & 3) * 16;
            const size_t gb = (size_t)(kt * 64 + r) * DK + db;
            #pragma unroll
            for (int u = 0; u < 4; u++) {
                float4 kv = *(const float4*)&Kb[gb + 4 * u];
                KsT[(db + 4 * u + 0) * AST + r] = kv.x;
                KsT[(db + 4 * u + 1) * AST + r] = kv.y;
                KsT[(db + 4 * u + 2) * AST + r] = kv.z;
                KsT[(db + 4 * u + 3) * AST + r] = kv.w;
                float4 vv = *(const float4*)&Vb[gb + 4 * u];
                *(float4*)&Vs[r * AST + db + 4 * u] = vv;
            }
        }
        __syncthreads();

        float sc[4][4];
        #pragma unroll
        for (int i = 0; i < 4; i++)
            #pragma unroll
            for (int j = 0; j < 4; j++) sc[i][j] = 0.f;

        #pragma unroll
        for (int d4 = 0; d4 < 16; d4++) {
            float qf[4][4];
            #pragma unroll
            for (int i = 0; i < 4; i++) {
                float4 qv = *(const float4*)&Qs[(4 * tr + i) * AST + 4 * d4];
                qf[i][0] = qv.x; qf[i][1] = qv.y; qf[i][2] = qv.z; qf[i][3] = qv.w;
            }
            #pragma unroll
            for (int u = 0; u < 4; u++) {
                float4 kv = *(const float4*)&KsT[(4 * d4 + u) * AST + 4 * tc];
                #pragma unroll
                for (int i = 0; i < 4; i++) {
                    sc[i][0] = fmaf(qf[i][u], kv.x, sc[i][0]);
                    sc[i][1] = fmaf(qf[i][u], kv.y, sc[i][1]);
                    sc[i][2] = fmaf(qf[i][u], kv.z, sc[i][2]);
                    sc[i][3] = fmaf(qf[i][u], kv.w, sc[i][3]);
                }
            }
        }

        {
            const int kjb = kt * 64 + 4 * tc;
            #pragma unroll
            for (int i = 0; i < 4; i++) {
                const int qi = q0 + 4 * tr + i;
                #pragma unroll
                for (int j = 0; j < 4; j++)
                    if (kjb + j >= qi) sc[i][j] = -1e30f;
            }
        }

        #pragma unroll
        for (int i = 0; i < 4; i++) {
            float mx = fmaxf(fmaxf(sc[i][0], sc[i][1]), fmaxf(sc[i][2], sc[i][3]));
            mx = rmax16(mx);
            const float mnew = fmaxf(m[i], mx);
            const float corr = __expf(m[i] - mnew);
            m[i] = mnew;
            float4 p;
            p.x = __expf(sc[i][0] - mnew);
            p.y = __expf(sc[i][1] - mnew);
            p.z = __expf(sc[i][2] - mnew);
            p.w = __expf(sc[i][3] - mnew);
            float rs = p.x + p.y + p.z + p.w;
            rs = rsum16(rs);
            l[i] = l[i] * corr + rs;
            #pragma unroll
            for (int j = 0; j < 4; j++) o[i][j] *= corr;
            *(float4*)&Ps[(4 * tr + i) * AST + 4 * tc] = p;
        }
        __syncthreads();

        #pragma unroll
        for (int k4 = 0; k4 < 16; k4++) {
            float pf[4][4];
            #pragma unroll
            for (int i = 0; i < 4; i++) {
                float4 pv = *(const float4*)&Ps[(4 * tr + i) * AST + 4 * k4];
                pf[i][0] = pv.x; pf[i][1] = pv.y; pf[i][2] = pv.z; pf[i][3] = pv.w;
            }
            #pragma unroll
            for (int u = 0; u < 4; u++) {
                float4 vv = *(const float4*)&Vs[(4 * k4 + u) * AST + 4 * tc];
                #pragma unroll
                for (int i = 0; i < 4; i++) {
                    o[i][0] = fmaf(pf[i][u], vv.x, o[i][0]);
                    o[i][1] = fmaf(pf[i][u], vv.y, o[i][1]);
                    o[i][2] = fmaf(pf[i][u], vv.z, o[i][2]);
                    o[i][3] = fmaf(pf[i][u], vv.w, o[i][3]);
                }
            }
        }
        __syncthreads();
    }

    const int b = bh >> 4, h = bh & 15;
    #pragma unroll
    for (int i = 0; i < 4; i++) {
        const int qi = q0 + 4 * tr + i;
        const float inv = (qi == 0) ? 0.f : (1.f / l[i]);
        float4 r;
        r.x = o[i][0] * inv; r.y = o[i][1] * inv;
        r.z = o[i][2] * inv; r.w = o[i][3] * inv;
        *(float4*)&ctx[((size_t)(b * SEQ + qi)) * D_MODEL + h * DK + 4 * tc] = r;
    }
}

// ---------------- layernorm ----------------
__global__ __launch_bounds__(256)
void ln_kernel(const float* __restrict__ X, const float* __restrict__ G,
               const float* __restrict__ Bt, float* __restrict__ O)
{
    __shared__ float ws[8], ws2[8];
    __shared__ float s_mu, s_rs;
    const int t = threadIdx.x;
    const size_t row = blockIdx.x;

    float4 v = *(const float4*)&X[row * D_MODEL + t * 4];
    float s  = v.x + v.y + v.z + v.w;
    float s2 = v.x * v.x + v.y * v.y + v.z * v.z + v.w * v.w;
    #pragma unroll
    for (int o = 16; o; o >>= 1) {
        s  += __shfl_xor_sync(0xffffffffu, s,  o);
        s2 += __shfl_xor_sync(0xffffffffu, s2, o);
    }
    if ((t & 31) == 0) { ws[t >> 5] = s; ws2[t >> 5] = s2; }
    __syncthreads();
    if (t == 0) {
        float S = 0.f, S2 = 0.f;
        #pragma unroll
        for (int w = 0; w < 8; w++) { S += ws[w]; S2 += ws2[w]; }
        const float mu  = S * (1.f / (float)D_MODEL);
        const float var = S2 * (1.f / (float)D_MODEL) - mu * mu;
        s_mu = mu;
        s_rs = rsqrtf(var + 1e-5f);
    }
    __syncthreads();
    const float mu = s_mu, rs = s_rs;

    float4 g = *(const float4*)&G[t * 4];
    float4 b = *(const float4*)&Bt[t * 4];
    float4 r;
    r.x = (v.x - mu) * rs * g.x + b.x;
    r.y = (v.y - mu) * rs * g.y + b.y;
    r.z = (v.z - mu) * rs * g.z + b.z;
    r.w = (v.w - mu) * rs * g.w + b.w;
    *(float4*)&O[row * D_MODEL + t * 4] = r;
}

// ---------------- orchestration ----------------
static inline void run_gemm_prep(const float* Aact, const float* W, int K, int N,
                                 __nv_bfloat16* abuf, __nv_bfloat16* wbuf)
{
    const int total4 = M_TOT * K / 4;
    act_split_kernel<<<(total4 + 255) / 256, 256>>>(Aact, abuf, K, total4);
    wt_split_kernel<<<dim3(K / 32, N / 32), 256>>>(W, wbuf, K, N);
}

extern "C" void kernel_launch(void* const* d_in, const int* in_sizes, int n_in,
                              void* d_out, int out_size)
{
    (void)in_sizes; (void)n_in; (void)out_size;

    const float* query = (const float*)d_in[0];
    const float* key_i = (const float*)d_in[1];
    const float* vals  = (const float*)d_in[2];
    const float* Wq = (const float*)d_in[3];
    const float* bq = (const float*)d_in[4];
    const float* Wk = (const float*)d_in[5];
    const float* bk = (const float*)d_in[6];
    const float* Wv = (const float*)d_in[7];
    const float* bv = (const float*)d_in[8];
    const float* Wo = (const float*)d_in[9];
    const float* bo = (const float*)d_in[10];
    const float* ln1g = (const float*)d_in[11];
    const float* ln1b = (const float*)d_in[12];
    const float* W1 = (const float*)d_in[13];
    const float* b1 = (const float*)d_in[14];
    const float* W2 = (const float*)d_in[15];
    const float* b2 = (const float*)d_in[16];
    const float* ln2g = (const float*)d_in[17];
    const float* ln2b = (const float*)d_in[18];
    float* out = (float*)d_out;

    float *pq, *pk, *pv, *pctx, *pt, *px, *ph;
    __nv_bfloat16 *pab, *pwb;
    cudaGetSymbolAddress((void**)&pq,   g_q);
    cudaGetSymbolAddress((void**)&pk,   g_k);
    cudaGetSymbolAddress((void**)&pv,   g_v);
    cudaGetSymbolAddress((void**)&pctx, g_ctx);
    cudaGetSymbolAddress((void**)&pt,   g_t);
    cudaGetSymbolAddress((void**)&px,   g_x);
    cudaGetSymbolAddress((void**)&ph,   g_h);
    cudaGetSymbolAddress((void**)&pab,  g_abuf);
    cudaGetSymbolAddress((void**)&pwb,  g_wbuf);

    cudaFuncSetAttribute(attn_kernel,
                         cudaFuncAttributeMaxDynamicSharedMemorySize, ATTN_SMEM);
    cudaFuncSetAttribute(tc_gemm<MODE_QKV>,
                         cudaFuncAttributeMaxDynamicSharedMemorySize, GEMM_SMEM);
    cudaFuncSetAttribute(tc_gemm<MODE_RELU>,
                         cudaFuncAttributeMaxDynamicSharedMemorySize, GEMM_SMEM);
    cudaFuncSetAttribute(tc_gemm<MODE_RES>,
                         cudaFuncAttributeMaxDynamicSharedMemorySize, GEMM_SMEM);

    const dim3 blk(256);
    const dim3 grid_1k(D_MODEL / 128, M_TOT / 128);   // (8, 32)
    const dim3 grid_4k(D_FF / 128,    M_TOT / 128);   // (32, 32)

    // QKV projections (bf16-split HMMA), scattered into [B,H,S,DK]
    run_gemm_prep(query, Wq, D_MODEL, D_MODEL, pab, pwb);
    tc_gemm<MODE_QKV><<<grid_1k, blk, GEMM_SMEM>>>(pab, pwb, bq, nullptr, pq, D_MODEL, 3 * D_MODEL);
    run_gemm_prep(key_i, Wk, D_MODEL, D_MODEL, pab, pwb);
    tc_gemm<MODE_QKV><<<grid_1k, blk, GEMM_SMEM>>>(pab, pwb, bk, nullptr, pk, D_MODEL, 3 * D_MODEL);
    run_gemm_prep(vals, Wv, D_MODEL, D_MODEL, pab, pwb);
    tc_gemm<MODE_QKV><<<grid_1k, blk, GEMM_SMEM>>>(pab, pwb, bv, nullptr, pv, D_MODEL, 3 * D_MODEL);

    // causal flash attention -> ctx [B,S,D]
    attn_kernel<<<dim3(SEQ / 64, NB * NH), blk, ATTN_SMEM>>>(pq, pk, pv, pctx);

    // attn_out = ctx @ Wo + bo + query -> g_t ; LN1 -> g_x
    run_gemm_prep(pctx, Wo, D_MODEL, D_MODEL, pab, pwb);
    tc_gemm<MODE_RES><<<grid_1k, blk, GEMM_SMEM>>>(pab, pwb, bo, query, pt, D_MODEL, 3 * D_MODEL);
    ln_kernel<<<M_TOT, 256>>>(pt, ln1g, ln1b, px);

    // FFN: h = relu(x @ W1 + b1) ; y = h @ W2 + b2 + x ; LN2 -> out
    run_gemm_prep(px, W1, D_MODEL, D_FF, pab, pwb);
    tc_gemm<MODE_RELU><<<grid_4k, blk, GEMM_SMEM>>>(pab, pwb, b1, nullptr, ph, D_FF, 3 * D_MODEL);
    run_gemm_prep(ph, W2, D_FF, D_MODEL, pab, pwb);
    tc_gemm<MODE_RES><<<grid_1k, blk, GEMM_SMEM>>>(pab, pwb, b2, px, pt, D_MODEL, 3 * D_FF);
    ln_kernel<<<M_TOT, 256>>>(pt, ln2g, ln2b, out);
}

// round 14
// speedup vs baseline: 1.3552x; 1.3552x over previous
#include <cuda_runtime.h>
#include <cuda_bf16.h>
#include <cstdint>
#include <math.h>

// ---------------- problem constants ----------------
#define D_MODEL 1024
#define D_FF    4096
#define NB      2
#define SEQ     2048
#define NH      16
#define DK      64
#define M_TOT   (NB*SEQ)          // 4096 rows

enum { MODE_QKV = 1, MODE_RELU = 2, MODE_RES = 3 };

// ---------------- scratch (static device arrays; no allocations) ----------------
__device__ float g_t  [M_TOT * D_MODEL];   // residual sums
__device__ float g_x  [M_TOT * D_MODEL];   // LN1 output (fp32, FFN2 residual)
__device__ __align__(128) __nv_bfloat16 g_qh[M_TOT * D_MODEL];  // [B,H,S,64] hi (pre-scaled)
__device__ __align__(128) __nv_bfloat16 g_ql[M_TOT * D_MODEL];
__device__ __align__(128) __nv_bfloat16 g_kh[M_TOT * D_MODEL];
__device__ __align__(128) __nv_bfloat16 g_kl[M_TOT * D_MODEL];
__device__ __align__(128) __nv_bfloat16 g_vh[M_TOT * D_MODEL];
__device__ __align__(128) __nv_bfloat16 g_vl[M_TOT * D_MODEL];
__device__ __align__(128) __nv_bfloat16 g_abuf[(size_t)M_TOT * 3 * D_MODEL];  // A' [M,3072]
__device__ __align__(128) __nv_bfloat16 g_hbuf[(size_t)M_TOT * 3 * D_FF];     // A' [M,12288]
__device__ __align__(128) __nv_bfloat16 g_wbuf[(size_t)D_FF * 3 * D_MODEL];   // B' (weights)

// ================= PTX helpers (baseline ISA: sm_80 features only) =================
__device__ __forceinline__ uint32_t smem_u32(const void* p) {
    uint32_t a;
    asm("{ .reg .u64 t; cvta.to.shared.u64 t, %1; cvt.u32.u64 %0, t; }" : "=r"(a) : "l"(p));
    return a;
}
__device__ __forceinline__ void cp_async16(uint32_t sdst, const void* gsrc) {
    asm volatile("cp.async.cg.shared.global [%0], [%1], 16;" :: "r"(sdst), "l"(gsrc));
}
#define CP_COMMIT() asm volatile("cp.async.commit_group;" ::: "memory")
#define CP_WAIT2()  asm volatile("cp.async.wait_group 2;" ::: "memory")
#define CP_WAIT1()  asm volatile("cp.async.wait_group 1;" ::: "memory")

#define SMEM_SWIZZLE_128B(off) ((off) ^ (((off) >> 3) & 0x70))

#define LDSM_X4(r, addr)                                                        \
    asm volatile("ldmatrix.sync.aligned.m8n8.x4.shared.b16 {%0,%1,%2,%3}, [%4];" \
                 : "=r"((r)[0]), "=r"((r)[1]), "=r"((r)[2]), "=r"((r)[3])        \
                 : "r"(addr))
#define LDSM_X4_T(r, addr)                                                            \
    asm volatile("ldmatrix.sync.aligned.m8n8.x4.trans.shared.b16 {%0,%1,%2,%3}, [%4];" \
                 : "=r"((r)[0]), "=r"((r)[1]), "=r"((r)[2]), "=r"((r)[3])              \
                 : "r"(addr))

__device__ __forceinline__ void mma_bf16(float* c, const uint32_t* a,
                                         uint32_t b0, uint32_t b1) {
    asm volatile("mma.sync.aligned.m16n8k16.row.col.f32.bf16.bf16.f32 "
                 "{%0,%1,%2,%3}, {%4,%5,%6,%7}, {%8,%9}, {%0,%1,%2,%3};"
                 : "+f"(c[0]), "+f"(c[1]), "+f"(c[2]), "+f"(c[3])
                 : "r"(a[0]), "r"(a[1]), "r"(a[2]), "r"(a[3]), "r"(b0), "r"(b1));
}

__device__ __forceinline__ uint32_t pack_bf16(float x, float y) {
    uint16_t a = __bfloat16_as_ushort(__float2bfloat16(x));
    uint16_t b = __bfloat16_as_ushort(__float2bfloat16(y));
    return (uint32_t)a | ((uint32_t)b << 16);
}
// hi = bf16(x),bf16(y) packed; lo = residuals packed
__device__ __forceinline__ void split_pack(float x, float y, uint32_t& hi, uint32_t& lo) {
    __nv_bfloat16 hx = __float2bfloat16(x), hy = __float2bfloat16(y);
    hi = (uint32_t)__bfloat16_as_ushort(hx) | ((uint32_t)__bfloat16_as_ushort(hy) << 16);
    lo = pack_bf16(x - __bfloat162float(hx), y - __bfloat162float(hy));
}

// ================= split-precision conversion kernels =================
// A' row = [A_hi | A_lo | A_hi]  (M x 3K), bf16
__global__ __launch_bounds__(256)
void act_split_kernel(const float* __restrict__ X, __nv_bfloat16* __restrict__ Y,
                      int K, int total4)
{
    int i = blockIdx.x * 256 + threadIdx.x;
    if (i >= total4) return;
    int idx = i << 2;
    float4 v = *(const float4*)&X[idx];
    int m = idx / K, k = idx - m * K;
    uint32_t h0, l0, h1, l1;
    split_pack(v.x, v.y, h0, l0);
    split_pack(v.z, v.w, h1, l1);
    size_t base = (size_t)m * 3 * K + k;
    uint2 hp = make_uint2(h0, h1), lp = make_uint2(l0, l1);
    *(uint2*)&Y[base]         = hp;
    *(uint2*)&Y[base + K]     = lp;
    *(uint2*)&Y[base + 2 * K] = hp;
}

// W [K,N] fp32 -> Y [N,3K] bf16 transposed: row = [B_hi | B_hi | B_lo]
__global__ __launch_bounds__(256)
void wt_split_kernel(const float* __restrict__ W, __nv_bfloat16* __restrict__ Y,
                     int K, int N)
{
    __shared__ float tile[32][33];
    const int tx = threadIdx.x & 31, ty = threadIdx.x >> 5;
    const int k0 = blockIdx.x * 32, n0 = blockIdx.y * 32;
    #pragma unroll
    for (int u = 0; u < 4; u++)
        tile[ty + 8 * u][tx] = W[(size_t)(k0 + ty + 8 * u) * N + n0 + tx];
    __syncthreads();
    #pragma unroll
    for (int u = 0; u < 4; u++) {
        const int n = n0 + ty + 8 * u;
        const float x = tile[tx][ty + 8 * u];
        const __nv_bfloat16 h = __float2bfloat16(x);
        const __nv_bfloat16 l = __float2bfloat16(x - __bfloat162float(h));
        const size_t base = (size_t)n * 3 * K + (k0 + tx);
        Y[base]         = h;
        Y[base + K]     = h;
        Y[base + 2 * K] = l;
    }
}

// ================= HMMA bf16 GEMM: C[M,N] = A'[M,Kp] @ B'[N,Kp]^T =================
#define GS          3
#define TILE_AB     16384
#define STAGE_BYTES (2 * TILE_AB)
#define GEMM_SMEM   (GS * STAGE_BYTES)    // 98304 B

template<int MODE>
__global__ __launch_bounds__(256, 2)
void tc_gemm(const __nv_bfloat16* __restrict__ A, const __nv_bfloat16* __restrict__ Bw,
             const float* __restrict__ bias, const float* __restrict__ Res,
             float* __restrict__ C,
             __nv_bfloat16* __restrict__ Oh, __nv_bfloat16* __restrict__ Ol,
             float scale, int N, int Kp)
{
    extern __shared__ __align__(1024) char smem[];
    const uint32_t tiles = smem_u32(smem);
    const int t    = threadIdx.x;
    const int lane = t & 31;
    const int wid  = t >> 5;
    const int wm   = wid >> 2;
    const int wn   = wid & 3;
    const int n0   = blockIdx.x * 128;
    const int m0   = blockIdx.y * 128;

#define LOAD_CHUNK(CH, ST) do {                                                        \
    const size_t kb = (size_t)(CH) * 128;                                              \
    const uint32_t aB = tiles + (ST) * STAGE_BYTES;                                    \
    const uint32_t bB = aB + TILE_AB;                                                  \
    _Pragma("unroll")                                                                  \
    for (int u = 0; u < 4; u++) {                                                      \
        const int idx = t + 256 * u;                                                   \
        const int row = idx >> 3;                                                      \
        const int c8  = (idx & 7) << 4;                                                \
        const uint32_t sw = SMEM_SWIZZLE_128B((uint32_t)(row * 128 + c8));             \
        cp_async16(aB + sw, (const char*)A  + (size_t)(m0 + row) * (size_t)Kp * 2 + kb + c8); \
        cp_async16(bB + sw, (const char*)Bw + (size_t)(n0 + row) * (size_t)Kp * 2 + kb + c8); \
    }                                                                                  \
    CP_COMMIT();                                                                       \
} while (0)

    const int nch = Kp >> 6;
    #pragma unroll
    for (int p = 0; p < GS; p++) LOAD_CHUNK(p, p);

    float acc[4][4][4];
    #pragma unroll
    for (int mt = 0; mt < 4; mt++)
        #pragma unroll
        for (int nt = 0; nt < 4; nt++)
            #pragma unroll
            for (int r = 0; r < 4; r++) acc[mt][nt][r] = 0.f;

    const int a_row = wm * 64 + (lane & 15);
    const int a_kb  = (lane >> 4) << 4;
    const int b_row = wn * 32 + (lane & 7) + ((lane >> 4) << 3);
    const int b_kb  = ((lane >> 3) & 1) << 4;

    #pragma unroll 1
    for (int c = 0; c < nch; c++) {
        const int st = c % GS;
        CP_WAIT2();
        __syncthreads();

        const uint32_t aB = tiles + st * STAGE_BYTES;
        const uint32_t bB = aB + TILE_AB;

        #pragma unroll
        for (int ks = 0; ks < 4; ks++) {
            uint32_t af[4][4];
            #pragma unroll
            for (int mt = 0; mt < 4; mt++) {
                const uint32_t off = SMEM_SWIZZLE_128B(
                    (uint32_t)((a_row + mt * 16) * 128 + ks * 32 + a_kb));
                LDSM_X4(af[mt], aB + off);
            }
            uint32_t bf[2][4];
            #pragma unroll
            for (int nt2 = 0; nt2 < 2; nt2++) {
                const uint32_t off = SMEM_SWIZZLE_128B(
                    (uint32_t)((b_row + nt2 * 16) * 128 + ks * 32 + b_kb));
                LDSM_X4(bf[nt2], bB + off);
            }
            #pragma unroll
            for (int mt = 0; mt < 4; mt++)
                #pragma unroll
                for (int nt = 0; nt < 4; nt++)
                    mma_bf16(acc[mt][nt], af[mt],
                             bf[nt >> 1][(nt & 1) * 2], bf[nt >> 1][(nt & 1) * 2 + 1]);
        }

        __syncthreads();
        if (c + GS < nch) LOAD_CHUNK(c + GS, st);
        else              CP_COMMIT();
    }
#undef LOAD_CHUNK

    // ---------------- epilogue ----------------
    const int qr = lane >> 2;
    const int qc = (lane & 3) << 1;
    #pragma unroll
    for (int mt = 0; mt < 4; mt++) {
        #pragma unroll
        for (int nt = 0; nt < 4; nt++) {
            const int col = n0 + wn * 32 + nt * 8 + qc;
            const float2 bv = *(const float2*)&bias[col];
            #pragma unroll
            for (int half = 0; half < 2; half++) {
                const int row = m0 + wm * 64 + mt * 16 + qr + half * 8;
                float rx = acc[mt][nt][half * 2 + 0] + bv.x;
                float ry = acc[mt][nt][half * 2 + 1] + bv.y;
                if (MODE == MODE_QKV) {
                    rx *= scale; ry *= scale;
                    uint32_t hi, lo;
                    split_pack(rx, ry, hi, lo);
                    const int h = col >> 6, d = col & 63;
                    const int bb = row >> 11, ss = row & 2047;
                    const size_t o = ((size_t)(bb * NH + h) * SEQ + ss) * DK + d;
                    *(uint32_t*)&Oh[o] = hi;
                    *(uint32_t*)&Ol[o] = lo;
                } else if (MODE == MODE_RELU) {
                    rx = fmaxf(rx, 0.f); ry = fmaxf(ry, 0.f);
                    uint32_t hi, lo;
                    split_pack(rx, ry, hi, lo);
                    const size_t base = (size_t)row * 3 * N;
                    *(uint32_t*)&Oh[base + col]         = hi;
                    *(uint32_t*)&Oh[base + N + col]     = lo;
                    *(uint32_t*)&Oh[base + 2 * N + col] = hi;
                } else { // MODE_RES
                    float2 rv = *(const float2*)&Res[(size_t)row * N + col];
                    float2 r = make_float2(rx + rv.x, ry + rv.y);
                    *(float2*)&C[(size_t)row * N + col] = r;
                }
            }
        }
    }
}

// ================= tensor-core flash attention =================
// CTA: 128 queries x 64-key blocks, 8 warps (16 q-rows each).
// S = Qhi*Khi + Qlo*Khi + Qhi*Klo (fp32 accum); softmax in regs;
// O += Phi*Vhi + Plo*Vhi + Phi*Vlo, P packed from accumulators.
#define SQH  0
#define SQL  16384
#define SKV0 32768
#define KV_STAGE 32768           // kh 0, kl 8192, vh 16384, vl 24576
#define ATTN_SMEM 98304

__global__ __launch_bounds__(256, 2)
void attn_tc(const __nv_bfloat16* __restrict__ Qh, const __nv_bfloat16* __restrict__ Ql,
             const __nv_bfloat16* __restrict__ Kh, const __nv_bfloat16* __restrict__ Kl,
             const __nv_bfloat16* __restrict__ Vh, const __nv_bfloat16* __restrict__ Vl,
             __nv_bfloat16* __restrict__ Actx)   // split A' rows, stride 3072
{
    extern __shared__ __align__(1024) char smem[];
    const uint32_t sb = smem_u32(smem);
    const int t = threadIdx.x, lane = t & 31, w = t >> 5;
    const int qt = gridDim.x - 1 - blockIdx.x;    // longest tiles first
    const int bh = blockIdx.y;
    const int q0 = qt * 128;

    const char* qhB = (const char*)(Qh + ((size_t)bh * SEQ + q0) * DK);
    const char* qlB = (const char*)(Ql + ((size_t)bh * SEQ + q0) * DK);
    const char* khB = (const char*)(Kh + (size_t)bh * SEQ * DK);
    const char* klB = (const char*)(Kl + (size_t)bh * SEQ * DK);
    const char* vhB = (const char*)(Vh + (size_t)bh * SEQ * DK);
    const char* vlB = (const char*)(Vl + (size_t)bh * SEQ * DK);

#define LOAD_KV(KB_, ST_) do {                                                   \
    const uint32_t stb = sb + SKV0 + (ST_) * KV_STAGE;                           \
    _Pragma("unroll")                                                            \
    for (int u = 0; u < 2; u++) {                                                \
        const int idx = t + 256 * u;                                             \
        const int row = idx >> 3;                                                \
        const int c8  = (idx & 7) << 4;                                          \
        const uint32_t sw = SMEM_SWIZZLE_128B((uint32_t)(row * 128 + c8));       \
        const size_t go = (size_t)((KB_) * 64 + row) * 128 + c8;                 \
        cp_async16(stb + sw,         khB + go);                                  \
        cp_async16(stb + 8192 + sw,  klB + go);                                  \
        cp_async16(stb + 16384 + sw, vhB + go);                                  \
        cp_async16(stb + 24576 + sw, vlB + go);                                  \
    }                                                                            \
} while (0)

    // group 0: Q planes + KV block 0
    #pragma unroll
    for (int u = 0; u < 4; u++) {
        const int idx = t + 256 * u;
        const int row = idx >> 3;
        const int c8  = (idx & 7) << 4;
        const uint32_t sw = SMEM_SWIZZLE_128B((uint32_t)(row * 128 + c8));
        cp_async16(sb + SQH + sw, qhB + (size_t)row * 128 + c8);
        cp_async16(sb + SQL + sw, qlB + (size_t)row * 128 + c8);
    }
    LOAD_KV(0, 0);
    CP_COMMIT();
    LOAD_KV(1, 1);        // every CTA has >= 2 key blocks
    CP_COMMIT();

    const int kbmax = (q0 + 126) >> 6;

    float O[8][4];
    #pragma unroll
    for (int nt = 0; nt < 8; nt++)
        #pragma unroll
        for (int j = 0; j < 4; j++) O[nt][j] = 0.f;
    float m0 = -1e30f, m1 = -1e30f, l0 = 0.f, l1 = 0.f;

    const int a_row = w * 16 + (lane & 15);
    const int a_kb  = (lane >> 4) << 4;
    const int bk_row = (lane & 7) + ((lane >> 4) << 3);
    const int bk_kb  = ((lane >> 3) & 1) << 4;
    const int v_row  = ((lane >> 3) & 1) * 8 + (lane & 7);
    const int v_cb   = (lane >> 4) << 4;

    #pragma unroll 1
    for (int kb = 0; kb <= kbmax; kb++) {
        const int st = kb & 1;
        CP_WAIT1();
        __syncthreads();
        const uint32_t KVB = sb + SKV0 + st * KV_STAGE;

        float sc[8][4];
        #pragma unroll
        for (int nt = 0; nt < 8; nt++)
            #pragma unroll
            for (int j = 0; j < 4; j++) sc[nt][j] = 0.f;

#define QK_PASS(QOFF, KOFF) do {                                                      \
    _Pragma("unroll")                                                                 \
    for (int ks = 0; ks < 4; ks++) {                                                  \
        uint32_t a[4];                                                                \
        LDSM_X4(a, sb + (QOFF) + SMEM_SWIZZLE_128B(                                   \
            (uint32_t)(a_row * 128 + ks * 32 + a_kb)));                               \
        uint32_t bq[4][4];                                                            \
        _Pragma("unroll")                                                             \
        for (int nt2 = 0; nt2 < 4; nt2++)                                             \
            LDSM_X4(bq[nt2], KVB + (KOFF) + SMEM_SWIZZLE_128B(                        \
                (uint32_t)((nt2 * 16 + bk_row) * 128 + ks * 32 + bk_kb)));            \
        _Pragma("unroll")                                                             \
        for (int nt = 0; nt < 8; nt++)                                                \
            mma_bf16(sc[nt], a, bq[nt >> 1][(nt & 1) * 2], bq[nt >> 1][(nt & 1) * 2 + 1]); \
    }                                                                                 \
} while (0)

        QK_PASS(SQH, 0);       // Qhi * Khi
        QK_PASS(SQL, 0);       // Qlo * Khi
        QK_PASS(SQH, 8192);    // Qhi * Klo
#undef QK_PASS

        // causal mask (strict j < i), only needed for the top-2 blocks
        if (kb >= 2 * qt) {
            const int cb0  = kb * 64 + 2 * (lane & 3);
            const int row0 = q0 + w * 16 + (lane >> 2);
            #pragma unroll
            for (int nt = 0; nt < 8; nt++) {
                const int cbase = cb0 + nt * 8;
                if (cbase + 0 >= row0)     sc[nt][0] = -1e30f;
                if (cbase + 1 >= row0)     sc[nt][1] = -1e30f;
                if (cbase + 0 >= row0 + 8) sc[nt][2] = -1e30f;
                if (cbase + 1 >= row0 + 8) sc[nt][3] = -1e30f;
            }
        }

        // online softmax
        float mx0 = -1e30f, mx1 = -1e30f;
        #pragma unroll
        for (int nt = 0; nt < 8; nt++) {
            mx0 = fmaxf(mx0, fmaxf(sc[nt][0], sc[nt][1]));
            mx1 = fmaxf(mx1, fmaxf(sc[nt][2], sc[nt][3]));
        }
        #pragma unroll
        for (int o = 1; o <= 2; o <<= 1) {
            mx0 = fmaxf(mx0, __shfl_xor_sync(0xffffffffu, mx0, o));
            mx1 = fmaxf(mx1, __shfl_xor_sync(0xffffffffu, mx1, o));
        }
        const float mn0 = fmaxf(m0, mx0), mn1 = fmaxf(m1, mx1);
        const float c0 = __expf(m0 - mn0), c1 = __expf(m1 - mn1);
        m0 = mn0; m1 = mn1;
        float rs0 = 0.f, rs1 = 0.f;
        #pragma unroll
        for (int nt = 0; nt < 8; nt++) {
            sc[nt][0] = __expf(sc[nt][0] - mn0);
            sc[nt][1] = __expf(sc[nt][1] - mn0);
            sc[nt][2] = __expf(sc[nt][2] - mn1);
            sc[nt][3] = __expf(sc[nt][3] - mn1);
            rs0 += sc[nt][0] + sc[nt][1];
            rs1 += sc[nt][2] + sc[nt][3];
        }
        #pragma unroll
        for (int o = 1; o <= 2; o <<= 1) {
            rs0 += __shfl_xor_sync(0xffffffffu, rs0, o);
            rs1 += __shfl_xor_sync(0xffffffffu, rs1, o);
        }
        l0 = l0 * c0 + rs0;
        l1 = l1 * c1 + rs1;
        #pragma unroll
        for (int nt = 0; nt < 8; nt++) {
            O[nt][0] *= c0; O[nt][1] *= c0;
            O[nt][2] *= c1; O[nt][3] *= c1;
        }

        // PV: O += Phi*Vhi + Plo*Vhi + Phi*Vlo
        #pragma unroll
        for (int kk = 0; kk < 4; kk++) {
            uint32_t ah[4], al[4];
            split_pack(sc[2*kk][0],   sc[2*kk][1],   ah[0], al[0]);
            split_pack(sc[2*kk][2],   sc[2*kk][3],   ah[1], al[1]);
            split_pack(sc[2*kk+1][0], sc[2*kk+1][1], ah[2], al[2]);
            split_pack(sc[2*kk+1][2], sc[2*kk+1][3], ah[3], al[3]);
            #pragma unroll
            for (int nt2 = 0; nt2 < 4; nt2++) {
                const uint32_t vaddr = SMEM_SWIZZLE_128B(
                    (uint32_t)((kk * 16 + v_row) * 128 + nt2 * 32 + v_cb));
                uint32_t bv[4];
                LDSM_X4_T(bv, KVB + 16384 + vaddr);   // Vhi^T frags
                mma_bf16(O[2*nt2],   ah, bv[0], bv[1]);
                mma_bf16(O[2*nt2+1], ah, bv[2], bv[3]);
                mma_bf16(O[2*nt2],   al, bv[0], bv[1]);
                mma_bf16(O[2*nt2+1], al, bv[2], bv[3]);
                LDSM_X4_T(bv, KVB + 24576 + vaddr);   // Vlo^T frags
                mma_bf16(O[2*nt2],   ah, bv[0], bv[1]);
                mma_bf16(O[2*nt2+1], ah, bv[2], bv[3]);
            }
        }

        __syncthreads();
        if (kb + 2 <= kbmax) LOAD_KV(kb + 2, st);
        CP_COMMIT();
    }
#undef LOAD_KV

    // epilogue: write split-A' ctx rows for the Wo GEMM
    const int b = bh >> 4, h = bh & 15;
    const int r0 = q0 + w * 16 + (lane >> 2);
    const int dc = 2 * (lane & 3);
    #pragma unroll
    for (int half = 0; half < 2; half++) {
        const int q = r0 + 8 * half;
        const float lv  = (half == 0) ? l0 : l1;
        const float inv = (q == 0) ? 0.f : (1.f / lv);
        const size_t rowb = ((size_t)b * SEQ + q) * 3072;
        #pragma unroll
        for (int nt = 0; nt < 8; nt++) {
            const float x = O[nt][half * 2 + 0] * inv;
            const float y = O[nt][half * 2 + 1] * inv;
            const int col = h * 64 + nt * 8 + dc;
            uint32_t hi, lo;
            split_pack(x, y, hi, lo);
            *(uint32_t*)&Actx[rowb + col]        = hi;
            *(uint32_t*)&Actx[rowb + 1024 + col] = lo;
            *(uint32_t*)&Actx[rowb + 2048 + col] = hi;
        }
    }
}

// ---------------- layernorm (optional split-A' side output) ----------------
__global__ __launch_bounds__(256)
void ln_kernel(const float* __restrict__ X, const float* __restrict__ G,
               const float* __restrict__ Bt, float* __restrict__ O,
               __nv_bfloat16* __restrict__ SP)
{
    __shared__ float ws[8], ws2[8];
    __shared__ float s_mu, s_rs;
    const int t = threadIdx.x;
    const size_t row = blockIdx.x;

    float4 v = *(const float4*)&X[row * D_MODEL + t * 4];
    float s  = v.x + v.y + v.z + v.w;
    float s2 = v.x * v.x + v.y * v.y + v.z * v.z + v.w * v.w;
    #pragma unroll
    for (int o = 16; o; o >>= 1) {
        s  += __shfl_xor_sync(0xffffffffu, s,  o);
        s2 += __shfl_xor_sync(0xffffffffu, s2, o);
    }
    if ((t & 31) == 0) { ws[t >> 5] = s; ws2[t >> 5] = s2; }
    __syncthreads();
    if (t == 0) {
        float S = 0.f, S2 = 0.f;
        #pragma unroll
        for (int w = 0; w < 8; w++) { S += ws[w]; S2 += ws2[w]; }
        const float mu  = S * (1.f / (float)D_MODEL);
        const float var = S2 * (1.f / (float)D_MODEL) - mu * mu;
        s_mu = mu;
        s_rs = rsqrtf(var + 1e-5f);
    }
    __syncthreads();
    const float mu = s_mu, rs = s_rs;

    float4 g = *(const float4*)&G[t * 4];
    float4 b = *(const float4*)&Bt[t * 4];
    float4 r;
    r.x = (v.x - mu) * rs * g.x + b.x;
    r.y = (v.y - mu) * rs * g.y + b.y;
    r.z = (v.z - mu) * rs * g.z + b.z;
    r.w = (v.w - mu) * rs * g.w + b.w;
    *(float4*)&O[row * D_MODEL + t * 4] = r;

    if (SP) {
        uint32_t h0, l0_, h1, l1_;
        split_pack(r.x, r.y, h0, l0_);
        split_pack(r.z, r.w, h1, l1_);
        const size_t base = row * 3072 + t * 4;
        uint2 hp = make_uint2(h0, h1), lp = make_uint2(l0_, l1_);
        *(uint2*)&SP[base]        = hp;
        *(uint2*)&SP[base + 1024] = lp;
        *(uint2*)&SP[base + 2048] = hp;
    }
}

// ---------------- orchestration ----------------
extern "C" void kernel_launch(void* const* d_in, const int* in_sizes, int n_in,
                              void* d_out, int out_size)
{
    (void)in_sizes; (void)n_in; (void)out_size;

    const float* query = (const float*)d_in[0];
    const float* key_i = (const float*)d_in[1];
    const float* vals  = (const float*)d_in[2];
    const float* Wq = (const float*)d_in[3];
    const float* bq = (const float*)d_in[4];
    const float* Wk = (const float*)d_in[5];
    const float* bk = (const float*)d_in[6];
    const float* Wv = (const float*)d_in[7];
    const float* bv = (const float*)d_in[8];
    const float* Wo = (const float*)d_in[9];
    const float* bo = (const float*)d_in[10];
    const float* ln1g = (const float*)d_in[11];
    const float* ln1b = (const float*)d_in[12];
    const float* W1 = (const float*)d_in[13];
    const float* b1 = (const float*)d_in[14];
    const float* W2 = (const float*)d_in[15];
    const float* b2 = (const float*)d_in[16];
    const float* ln2g = (const float*)d_in[17];
    const float* ln2b = (const float*)d_in[18];
    float* out = (float*)d_out;

    float *pt, *px;
    __nv_bfloat16 *pqh, *pql, *pkh, *pkl, *pvh, *pvl, *pab, *phb, *pwb;
    cudaGetSymbolAddress((void**)&pt,  g_t);
    cudaGetSymbolAddress((void**)&px,  g_x);
    cudaGetSymbolAddress((void**)&pqh, g_qh);
    cudaGetSymbolAddress((void**)&pql, g_ql);
    cudaGetSymbolAddress((void**)&pkh, g_kh);
    cudaGetSymbolAddress((void**)&pkl, g_kl);
    cudaGetSymbolAddress((void**)&pvh, g_vh);
    cudaGetSymbolAddress((void**)&pvl, g_vl);
    cudaGetSymbolAddress((void**)&pab, g_abuf);
    cudaGetSymbolAddress((void**)&phb, g_hbuf);
    cudaGetSymbolAddress((void**)&pwb, g_wbuf);

    cudaFuncSetAttribute(attn_tc,
                         cudaFuncAttributeMaxDynamicSharedMemorySize, ATTN_SMEM);
    cudaFuncSetAttribute(tc_gemm<MODE_QKV>,
                         cudaFuncAttributeMaxDynamicSharedMemorySize, GEMM_SMEM);
    cudaFuncSetAttribute(tc_gemm<MODE_RELU>,
                         cudaFuncAttributeMaxDynamicSharedMemorySize, GEMM_SMEM);
    cudaFuncSetAttribute(tc_gemm<MODE_RES>,
                         cudaFuncAttributeMaxDynamicSharedMemorySize, GEMM_SMEM);

    const dim3 blk(256);
    const dim3 grid_1k(D_MODEL / 128, M_TOT / 128);   // (8, 32)
    const dim3 grid_4k(D_FF / 128,    M_TOT / 128);   // (32, 32)
    const int total4_1k = M_TOT * D_MODEL / 4;

    // ---- QKV projections -> split bf16 [B,H,S,64] hi/lo (Q pre-scaled by 1/8) ----
    act_split_kernel<<<(total4_1k + 255) / 256, 256>>>(query, pab, D_MODEL, total4_1k);
    wt_split_kernel<<<dim3(D_MODEL / 32, D_MODEL / 32), 256>>>(Wq, pwb, D_MODEL, D_MODEL);
    tc_gemm<MODE_QKV><<<grid_1k, blk, GEMM_SMEM>>>(pab, pwb, bq, nullptr, nullptr,
                                                   pqh, pql, 0.125f, D_MODEL, 3 * D_MODEL);
    act_split_kernel<<<(total4_1k + 255) / 256, 256>>>(key_i, pab, D_MODEL, total4_1k);
    wt_split_kernel<<<dim3(D_MODEL / 32, D_MODEL / 32), 256>>>(Wk, pwb, D_MODEL, D_MODEL);
    tc_gemm<MODE_QKV><<<grid_1k, blk, GEMM_SMEM>>>(pab, pwb, bk, nullptr, nullptr,
                                                   pkh, pkl, 1.0f, D_MODEL, 3 * D_MODEL);
    act_split_kernel<<<(total4_1k + 255) / 256, 256>>>(vals, pab, D_MODEL, total4_1k);
    wt_split_kernel<<<dim3(D_MODEL / 32, D_MODEL / 32), 256>>>(Wv, pwb, D_MODEL, D_MODEL);
    tc_gemm<MODE_QKV><<<grid_1k, blk, GEMM_SMEM>>>(pab, pwb, bv, nullptr, nullptr,
                                                   pvh, pvl, 1.0f, D_MODEL, 3 * D_MODEL);

    // ---- tensor-core causal flash attention -> split ctx A' in g_abuf ----
    attn_tc<<<dim3(SEQ / 128, NB * NH), blk, ATTN_SMEM>>>(pqh, pql, pkh, pkl, pvh, pvl, pab);

    // ---- Wo + residual(query) -> g_t ; LN1 -> g_x (fp32) + split A' in g_abuf ----
    wt_split_kernel<<<dim3(D_MODEL / 32, D_MODEL / 32), 256>>>(Wo, pwb, D_MODEL, D_MODEL);
    tc_gemm<MODE_RES><<<grid_1k, blk, GEMM_SMEM>>>(pab, pwb, bo, query, pt,
                                                   nullptr, nullptr, 1.0f, D_MODEL, 3 * D_MODEL);
    ln_kernel<<<M_TOT, 256>>>(pt, ln1g, ln1b, px, pab);

    // ---- FFN1: relu(x@W1+b1) -> split A' in g_hbuf ----
    wt_split_kernel<<<dim3(D_MODEL / 32, D_FF / 32), 256>>>(W1, pwb, D_MODEL, D_FF);
    tc_gemm<MODE_RELU><<<grid_4k, blk, GEMM_SMEM>>>(pab, pwb, b1, nullptr, nullptr,
                                                    phb, nullptr, 1.0f, D_FF, 3 * D_MODEL);

    // ---- FFN2 + residual(x) -> g_t ; LN2 -> out ----
    wt_split_kernel<<<dim3(D_FF / 32, D_MODEL / 32), 256>>>(W2, pwb, D_FF, D_MODEL);
    tc_gemm<MODE_RES><<<grid_1k, blk, GEMM_SMEM>>>(phb, pwb, b2, px, pt,
                                                   nullptr, nullptr, 1.0f, D_MODEL, 3 * D_FF);
    ln_kernel<<<M_TOT, 256>>>(pt, ln2g, ln2b, out, nullptr);
}

// round 15
// speedup vs baseline: 1.3851x; 1.0221x over previous
#include <cuda_runtime.h>
#include <cuda_bf16.h>
#include <cstdint>
#include <math.h>

// ---------------- problem constants ----------------
#define D_MODEL 1024
#define D_FF    4096
#define NB      2
#define SEQ     2048
#define NH      16
#define DK      64
#define M_TOT   (NB*SEQ)          // 4096 rows

enum { MODE_QKV = 1, MODE_RELU = 2, MODE_RES = 3 };

// ---------------- scratch (static device arrays; no allocations) ----------------
__device__ float g_t  [M_TOT * D_MODEL];   // residual sums
__device__ float g_x  [M_TOT * D_MODEL];   // LN1 output (fp32, FFN2 residual)
__device__ __align__(128) __nv_bfloat16 g_qh[M_TOT * D_MODEL];  // [B,H,S,64] hi (pre-scaled)
__device__ __align__(128) __nv_bfloat16 g_ql[M_TOT * D_MODEL];
__device__ __align__(128) __nv_bfloat16 g_kh[M_TOT * D_MODEL];
__device__ __align__(128) __nv_bfloat16 g_kl[M_TOT * D_MODEL];
__device__ __align__(128) __nv_bfloat16 g_vh[M_TOT * D_MODEL];
__device__ __align__(128) __nv_bfloat16 g_vl[M_TOT * D_MODEL];
__device__ __align__(128) __nv_bfloat16 g_abuf[(size_t)M_TOT * 2 * D_MODEL];  // A [M,2048]
__device__ __align__(128) __nv_bfloat16 g_hbuf[(size_t)M_TOT * 2 * D_FF];     // A [M,8192]
__device__ __align__(128) __nv_bfloat16 g_wbuf[(size_t)2 * D_FF * D_MODEL];   // B (weights)

// ================= PTX helpers (baseline ISA: sm_80 features only) =================
__device__ __forceinline__ uint32_t smem_u32(const void* p) {
    uint32_t a;
    asm("{ .reg .u64 t; cvta.to.shared.u64 t, %1; cvt.u32.u64 %0, t; }" : "=r"(a) : "l"(p));
    return a;
}
__device__ __forceinline__ void cp_async16(uint32_t sdst, const void* gsrc) {
    asm volatile("cp.async.cg.shared.global [%0], [%1], 16;" :: "r"(sdst), "l"(gsrc));
}
#define CP_COMMIT() asm volatile("cp.async.commit_group;" ::: "memory")
#define CP_WAIT1()  asm volatile("cp.async.wait_group 1;" ::: "memory")

#define SMEM_SWIZZLE_128B(off) ((off) ^ (((off) >> 3) & 0x70))

#define LDSM_X4(r, addr)                                                        \
    asm volatile("ldmatrix.sync.aligned.m8n8.x4.shared.b16 {%0,%1,%2,%3}, [%4];" \
                 : "=r"((r)[0]), "=r"((r)[1]), "=r"((r)[2]), "=r"((r)[3])        \
                 : "r"(addr))
#define LDSM_X4_T(r, addr)                                                            \
    asm volatile("ldmatrix.sync.aligned.m8n8.x4.trans.shared.b16 {%0,%1,%2,%3}, [%4];" \
                 : "=r"((r)[0]), "=r"((r)[1]), "=r"((r)[2]), "=r"((r)[3])              \
                 : "r"(addr))

__device__ __forceinline__ void mma_bf16(float* c, const uint32_t* a,
                                         uint32_t b0, uint32_t b1) {
    asm volatile("mma.sync.aligned.m16n8k16.row.col.f32.bf16.bf16.f32 "
                 "{%0,%1,%2,%3}, {%4,%5,%6,%7}, {%8,%9}, {%0,%1,%2,%3};"
                 : "+f"(c[0]), "+f"(c[1]), "+f"(c[2]), "+f"(c[3])
                 : "r"(a[0]), "r"(a[1]), "r"(a[2]), "r"(a[3]), "r"(b0), "r"(b1));
}

__device__ __forceinline__ uint32_t pack_bf16(float x, float y) {
    uint16_t a = __bfloat16_as_ushort(__float2bfloat16(x));
    uint16_t b = __bfloat16_as_ushort(__float2bfloat16(y));
    return (uint32_t)a | ((uint32_t)b << 16);
}
__device__ __forceinline__ void split_pack(float x, float y, uint32_t& hi, uint32_t& lo) {
    __nv_bfloat16 hx = __float2bfloat16(x), hy = __float2bfloat16(y);
    hi = (uint32_t)__bfloat16_as_ushort(hx) | ((uint32_t)__bfloat16_as_ushort(hy) << 16);
    lo = pack_bf16(x - __bfloat162float(hx), y - __bfloat162float(hy));
}

// ================= split-precision conversion kernels =================
// A row = [A_hi | A_lo]  (M x 2K), bf16
__global__ __launch_bounds__(256)
void act_split_kernel(const float* __restrict__ X, __nv_bfloat16* __restrict__ Y,
                      int K, int total4)
{
    int i = blockIdx.x * 256 + threadIdx.x;
    if (i >= total4) return;
    int idx = i << 2;
    float4 v = *(const float4*)&X[idx];
    int m = idx / K, k = idx - m * K;
    uint32_t h0, l0, h1, l1;
    split_pack(v.x, v.y, h0, l0);
    split_pack(v.z, v.w, h1, l1);
    size_t base = (size_t)m * 2 * K + k;
    *(uint2*)&Y[base]     = make_uint2(h0, h1);
    *(uint2*)&Y[base + K] = make_uint2(l0, l1);
}

// W [K,N] fp32 -> Y [N,2K] bf16 transposed: row = [B_hi | B_lo]
__global__ __launch_bounds__(256)
void wt_split_kernel(const float* __restrict__ W, __nv_bfloat16* __restrict__ Y,
                     int K, int N)
{
    __shared__ float tile[32][33];
    const int tx = threadIdx.x & 31, ty = threadIdx.x >> 5;
    const int k0 = blockIdx.x * 32, n0 = blockIdx.y * 32;
    #pragma unroll
    for (int u = 0; u < 4; u++)
        tile[ty + 8 * u][tx] = W[(size_t)(k0 + ty + 8 * u) * N + n0 + tx];
    __syncthreads();
    #pragma unroll
    for (int u = 0; u < 4; u++) {
        const int n = n0 + ty + 8 * u;
        const float x = tile[tx][ty + 8 * u];
        const __nv_bfloat16 h = __float2bfloat16(x);
        const __nv_bfloat16 l = __float2bfloat16(x - __bfloat162float(h));
        const size_t base = (size_t)n * 2 * K + (k0 + tx);
        Y[base]     = h;
        Y[base + K] = l;
    }
}

// ================= HMMA bf16 GEMM: C = A_hi@B_hi^T + A_lo@B_hi^T + A_hi@B_lo^T =================
// 256x128 CTA tile, 512 threads (16 warps, 4x4 of 64x32), K-chunk = 64 real K,
// 2-stage cp.async pipeline; stage holds {a_hi, a_lo, b_hi, b_lo}.
#define S_AH 0
#define S_AL 32768
#define S_BH 65536
#define S_BL 81920
#define STAGE_BYTES 98304
#define GEMM_SMEM   (2 * STAGE_BYTES)   // 196608

template<int MODE>
__global__ __launch_bounds__(512, 1)
void tc_gemm(const __nv_bfloat16* __restrict__ A, const __nv_bfloat16* __restrict__ Bw,
             const float* __restrict__ bias, const float* __restrict__ Res,
             float* __restrict__ C,
             __nv_bfloat16* __restrict__ Oh, __nv_bfloat16* __restrict__ Ol,
             float scale, int N, int Kr)
{
    extern __shared__ __align__(1024) char smem[];
    const uint32_t tiles = smem_u32(smem);
    const int t    = threadIdx.x;
    const int lane = t & 31;
    const int wid  = t >> 5;
    const int wm   = wid >> 2;          // 0..3 (64 rows each)
    const int wn   = wid & 3;           // 0..3 (32 cols each)
    const int n0   = blockIdx.x * 128;
    const int m0   = blockIdx.y * 256;
    const size_t rowB = (size_t)2 * Kr * 2;   // bytes per A/B row
    const size_t loOf = (size_t)Kr * 2;       // byte offset to lo plane

#define LOAD_CHUNK(CH, ST) do {                                                        \
    const uint32_t stb = tiles + (ST) * STAGE_BYTES;                                   \
    const size_t kb = (size_t)(CH) * 128;                                              \
    _Pragma("unroll")                                                                  \
    for (int u = 0; u < 4; u++) {                                                      \
        const int idx = t + 512 * u;                                                   \
        const int row = idx >> 3;                                                      \
        const int c8  = (idx & 7) << 4;                                                \
        const uint32_t sw = SMEM_SWIZZLE_128B((uint32_t)(row * 128 + c8));             \
        const char* ap = (const char*)A + (size_t)(m0 + row) * rowB + kb + c8;         \
        cp_async16(stb + S_AH + sw, ap);                                               \
        cp_async16(stb + S_AL + sw, ap + loOf);                                        \
    }                                                                                  \
    _Pragma("unroll")                                                                  \
    for (int u = 0; u < 2; u++) {                                                      \
        const int idx = t + 512 * u;                                                   \
        const int row = idx >> 3;                                                      \
        const int c8  = (idx & 7) << 4;                                                \
        const uint32_t sw = SMEM_SWIZZLE_128B((uint32_t)(row * 128 + c8));             \
        const char* bp = (const char*)Bw + (size_t)(n0 + row) * rowB + kb + c8;        \
        cp_async16(stb + S_BH + sw, bp);                                               \
        cp_async16(stb + S_BL + sw, bp + loOf);                                        \
    }                                                                                  \
    CP_COMMIT();                                                                       \
} while (0)

    const int nch = Kr >> 6;
    LOAD_CHUNK(0, 0);
    LOAD_CHUNK(1, 1);

    float acc[4][4][4];
    #pragma unroll
    for (int mt = 0; mt < 4; mt++)
        #pragma unroll
        for (int nt = 0; nt < 4; nt++)
            #pragma unroll
            for (int r = 0; r < 4; r++) acc[mt][nt][r] = 0.f;

    const int a_row = wm * 64 + (lane & 15);
    const int a_kb  = (lane >> 4) << 4;
    const int b_row = wn * 32 + (lane & 7) + ((lane >> 4) << 3);
    const int b_kb  = ((lane >> 3) & 1) << 4;

    #pragma unroll 1
    for (int c = 0; c < nch; c++) {
        const int st = c & 1;
        CP_WAIT1();
        __syncthreads();
        const uint32_t stb = tiles + st * STAGE_BYTES;

        #pragma unroll
        for (int ks = 0; ks < 4; ks++) {
            uint32_t ah[4][4], al[4][4];
            #pragma unroll
            for (int mt = 0; mt < 4; mt++) {
                const uint32_t off = SMEM_SWIZZLE_128B(
                    (uint32_t)((a_row + mt * 16) * 128 + ks * 32 + a_kb));
                LDSM_X4(ah[mt], stb + S_AH + off);
                LDSM_X4(al[mt], stb + S_AL + off);
            }
            uint32_t bh[2][4];
            #pragma unroll
            for (int nt2 = 0; nt2 < 2; nt2++) {
                const uint32_t off = SMEM_SWIZZLE_128B(
                    (uint32_t)((b_row + nt2 * 16) * 128 + ks * 32 + b_kb));
                LDSM_X4(bh[nt2], stb + S_BH + off);
            }
            #pragma unroll
            for (int mt = 0; mt < 4; mt++)
                #pragma unroll
                for (int nt = 0; nt < 4; nt++)
                    mma_bf16(acc[mt][nt], ah[mt],
                             bh[nt >> 1][(nt & 1) * 2], bh[nt >> 1][(nt & 1) * 2 + 1]);
            #pragma unroll
            for (int mt = 0; mt < 4; mt++)
                #pragma unroll
                for (int nt = 0; nt < 4; nt++)
                    mma_bf16(acc[mt][nt], al[mt],
                             bh[nt >> 1][(nt & 1) * 2], bh[nt >> 1][(nt & 1) * 2 + 1]);
            uint32_t bl[2][4];
            #pragma unroll
            for (int nt2 = 0; nt2 < 2; nt2++) {
                const uint32_t off = SMEM_SWIZZLE_128B(
                    (uint32_t)((b_row + nt2 * 16) * 128 + ks * 32 + b_kb));
                LDSM_X4(bl[nt2], stb + S_BL + off);
            }
            #pragma unroll
            for (int mt = 0; mt < 4; mt++)
                #pragma unroll
                for (int nt = 0; nt < 4; nt++)
                    mma_bf16(acc[mt][nt], ah[mt],
                             bl[nt >> 1][(nt & 1) * 2], bl[nt >> 1][(nt & 1) * 2 + 1]);
        }

        __syncthreads();
        if (c + 2 < nch) LOAD_CHUNK(c + 2, st);
        else             CP_COMMIT();
    }
#undef LOAD_CHUNK

    // ---------------- epilogue ----------------
    const int qr = lane >> 2;
    const int qc = (lane & 3) << 1;
    #pragma unroll
    for (int mt = 0; mt < 4; mt++) {
        #pragma unroll
        for (int nt = 0; nt < 4; nt++) {
            const int col = n0 + wn * 32 + nt * 8 + qc;
            const float2 bv = *(const float2*)&bias[col];
            #pragma unroll
            for (int half = 0; half < 2; half++) {
                const int row = m0 + wm * 64 + mt * 16 + qr + half * 8;
                float rx = acc[mt][nt][half * 2 + 0] + bv.x;
                float ry = acc[mt][nt][half * 2 + 1] + bv.y;
                if (MODE == MODE_QKV) {
                    rx *= scale; ry *= scale;
                    uint32_t hi, lo;
                    split_pack(rx, ry, hi, lo);
                    const int h = col >> 6, d = col & 63;
                    const int bb = row >> 11, ss = row & 2047;
                    const size_t o = ((size_t)(bb * NH + h) * SEQ + ss) * DK + d;
                    *(uint32_t*)&Oh[o] = hi;
                    *(uint32_t*)&Ol[o] = lo;
                } else if (MODE == MODE_RELU) {
                    rx = fmaxf(rx, 0.f); ry = fmaxf(ry, 0.f);
                    uint32_t hi, lo;
                    split_pack(rx, ry, hi, lo);
                    const size_t base = (size_t)row * 2 * N;
                    *(uint32_t*)&Oh[base + col]     = hi;
                    *(uint32_t*)&Oh[base + N + col] = lo;
                } else { // MODE_RES
                    float2 rv = *(const float2*)&Res[(size_t)row * N + col];
                    float2 r = make_float2(rx + rv.x, ry + rv.y);
                    *(float2*)&C[(size_t)row * N + col] = r;
                }
            }
        }
    }
}

// ================= tensor-core flash attention =================
// CTA: 128 queries x 64-key blocks, 8 warps (16 q-rows each).
#define SQH  0
#define SQL  16384
#define SKV0 32768
#define KV_STAGE 32768           // kh 0, kl 8192, vh 16384, vl 24576
#define ATTN_SMEM 98304

__global__ __launch_bounds__(256, 2)
void attn_tc(const __nv_bfloat16* __restrict__ Qh, const __nv_bfloat16* __restrict__ Ql,
             const __nv_bfloat16* __restrict__ Kh, const __nv_bfloat16* __restrict__ Kl,
             const __nv_bfloat16* __restrict__ Vh, const __nv_bfloat16* __restrict__ Vl,
             __nv_bfloat16* __restrict__ Actx)   // split A rows, stride 2048
{
    extern __shared__ __align__(1024) char smem[];
    const uint32_t sb = smem_u32(smem);
    const int t = threadIdx.x, lane = t & 31, w = t >> 5;
    const int qt = gridDim.x - 1 - blockIdx.x;
    const int bh = blockIdx.y;
    const int q0 = qt * 128;

    const char* qhB = (const char*)(Qh + ((size_t)bh * SEQ + q0) * DK);
    const char* qlB = (const char*)(Ql + ((size_t)bh * SEQ + q0) * DK);
    const char* khB = (const char*)(Kh + (size_t)bh * SEQ * DK);
    const char* klB = (const char*)(Kl + (size_t)bh * SEQ * DK);
    const char* vhB = (const char*)(Vh + (size_t)bh * SEQ * DK);
    const char* vlB = (const char*)(Vl + (size_t)bh * SEQ * DK);

#define LOAD_KV(KB_, ST_) do {                                                   \
    const uint32_t stb = sb + SKV0 + (ST_) * KV_STAGE;                           \
    _Pragma("unroll")                                                            \
    for (int u = 0; u < 2; u++) {                                                \
        const int idx = t + 256 * u;                                             \
        const int row = idx >> 3;                                                \
        const int c8  = (idx & 7) << 4;                                          \
        const uint32_t sw = SMEM_SWIZZLE_128B((uint32_t)(row * 128 + c8));       \
        const size_t go = (size_t)((KB_) * 64 + row) * 128 + c8;                 \
        cp_async16(stb + sw,         khB + go);                                  \
        cp_async16(stb + 8192 + sw,  klB + go);                                  \
        cp_async16(stb + 16384 + sw, vhB + go);                                  \
        cp_async16(stb + 24576 + sw, vlB + go);                                  \
    }                                                                            \
} while (0)

    #pragma unroll
    for (int u = 0; u < 4; u++) {
        const int idx = t + 256 * u;
        const int row = idx >> 3;
        const int c8  = (idx & 7) << 4;
        const uint32_t sw = SMEM_SWIZZLE_128B((uint32_t)(row * 128 + c8));
        cp_async16(sb + SQH + sw, qhB + (size_t)row * 128 + c8);
        cp_async16(sb + SQL + sw, qlB + (size_t)row * 128 + c8);
    }
    LOAD_KV(0, 0);
    CP_COMMIT();
    LOAD_KV(1, 1);
    CP_COMMIT();

    const int kbmax = (q0 + 126) >> 6;

    float O[8][4];
    #pragma unroll
    for (int nt = 0; nt < 8; nt++)
        #pragma unroll
        for (int j = 0; j < 4; j++) O[nt][j] = 0.f;
    float m0 = -1e30f, m1 = -1e30f, l0 = 0.f, l1 = 0.f;

    const int a_row = w * 16 + (lane & 15);
    const int a_kb  = (lane >> 4) << 4;
    const int bk_row = (lane & 7) + ((lane >> 4) << 3);
    const int bk_kb  = ((lane >> 3) & 1) << 4;
    const int v_row  = ((lane >> 3) & 1) * 8 + (lane & 7);
    const int v_cb   = (lane >> 4) << 4;

    #pragma unroll 1
    for (int kb = 0; kb <= kbmax; kb++) {
        const int st = kb & 1;
        CP_WAIT1();
        __syncthreads();
        const uint32_t KVB = sb + SKV0 + st * KV_STAGE;

        float sc[8][4];
        #pragma unroll
        for (int nt = 0; nt < 8; nt++)
            #pragma unroll
            for (int j = 0; j < 4; j++) sc[nt][j] = 0.f;

#define QK_PASS(QOFF, KOFF) do {                                                      \
    _Pragma("unroll")                                                                 \
    for (int ks = 0; ks < 4; ks++) {                                                  \
        uint32_t a[4];                                                                \
        LDSM_X4(a, sb + (QOFF) + SMEM_SWIZZLE_128B(                                   \
            (uint32_t)(a_row * 128 + ks * 32 + a_kb)));                               \
        uint32_t bq[4][4];                                                            \
        _Pragma("unroll")                                                             \
        for (int nt2 = 0; nt2 < 4; nt2++)                                             \
            LDSM_X4(bq[nt2], KVB + (KOFF) + SMEM_SWIZZLE_128B(                        \
                (uint32_t)((nt2 * 16 + bk_row) * 128 + ks * 32 + bk_kb)));            \
        _Pragma("unroll")                                                             \
        for (int nt = 0; nt < 8; nt++)                                                \
            mma_bf16(sc[nt], a, bq[nt >> 1][(nt & 1) * 2], bq[nt >> 1][(nt & 1) * 2 + 1]); \
    }                                                                                 \
} while (0)

        QK_PASS(SQH, 0);
        QK_PASS(SQL, 0);
        QK_PASS(SQH, 8192);
#undef QK_PASS

        if (kb >= 2 * qt) {
            const int cb0  = kb * 64 + 2 * (lane & 3);
            const int row0 = q0 + w * 16 + (lane >> 2);
            #pragma unroll
            for (int nt = 0; nt < 8; nt++) {
                const int cbase = cb0 + nt * 8;
                if (cbase + 0 >= row0)     sc[nt][0] = -1e30f;
                if (cbase + 1 >= row0)     sc[nt][1] = -1e30f;
                if (cbase + 0 >= row0 + 8) sc[nt][2] = -1e30f;
                if (cbase + 1 >= row0 + 8) sc[nt][3] = -1e30f;
            }
        }

        float mx0 = -1e30f, mx1 = -1e30f;
        #pragma unroll
        for (int nt = 0; nt < 8; nt++) {
            mx0 = fmaxf(mx0, fmaxf(sc[nt][0], sc[nt][1]));
            mx1 = fmaxf(mx1, fmaxf(sc[nt][2], sc[nt][3]));
        }
        #pragma unroll
        for (int o = 1; o <= 2; o <<= 1) {
            mx0 = fmaxf(mx0, __shfl_xor_sync(0xffffffffu, mx0, o));
            mx1 = fmaxf(mx1, __shfl_xor_sync(0xffffffffu, mx1, o));
        }
        const float mn0 = fmaxf(m0, mx0), mn1 = fmaxf(m1, mx1);
        const float c0 = __expf(m0 - mn0), c1 = __expf(m1 - mn1);
        m0 = mn0; m1 = mn1;
        float rs0 = 0.f, rs1 = 0.f;
        #pragma unroll
        for (int nt = 0; nt < 8; nt++) {
            sc[nt][0] = __expf(sc[nt][0] - mn0);
            sc[nt][1] = __expf(sc[nt][1] - mn0);
            sc[nt][2] = __expf(sc[nt][2] - mn1);
            sc[nt][3] = __expf(sc[nt][3] - mn1);
            rs0 += sc[nt][0] + sc[nt][1];
            rs1 += sc[nt][2] + sc[nt][3];
        }
        #pragma unroll
        for (int o = 1; o <= 2; o <<= 1) {
            rs0 += __shfl_xor_sync(0xffffffffu, rs0, o);
            rs1 += __shfl_xor_sync(0xffffffffu, rs1, o);
        }
        l0 = l0 * c0 + rs0;
        l1 = l1 * c1 + rs1;
        #pragma unroll
        for (int nt = 0; nt < 8; nt++) {
            O[nt][0] *= c0; O[nt][1] *= c0;
            O[nt][2] *= c1; O[nt][3] *= c1;
        }

        #pragma unroll
        for (int kk = 0; kk < 4; kk++) {
            uint32_t ah[4], al[4];
            split_pack(sc[2*kk][0],   sc[2*kk][1],   ah[0], al[0]);
            split_pack(sc[2*kk][2],   sc[2*kk][3],   ah[1], al[1]);
            split_pack(sc[2*kk+1][0], sc[2*kk+1][1], ah[2], al[2]);
            split_pack(sc[2*kk+1][2], sc[2*kk+1][3], ah[3], al[3]);
            #pragma unroll
            for (int nt2 = 0; nt2 < 4; nt2++) {
                const uint32_t vaddr = SMEM_SWIZZLE_128B(
                    (uint32_t)((kk * 16 + v_row) * 128 + nt2 * 32 + v_cb));
                uint32_t bv[4];
                LDSM_X4_T(bv, KVB + 16384 + vaddr);
                mma_bf16(O[2*nt2],   ah, bv[0], bv[1]);
                mma_bf16(O[2*nt2+1], ah, bv[2], bv[3]);
                mma_bf16(O[2*nt2],   al, bv[0], bv[1]);
                mma_bf16(O[2*nt2+1], al, bv[2], bv[3]);
                LDSM_X4_T(bv, KVB + 24576 + vaddr);
                mma_bf16(O[2*nt2],   ah, bv[0], bv[1]);
                mma_bf16(O[2*nt2+1], ah, bv[2], bv[3]);
            }
        }

        __syncthreads();
        if (kb + 2 <= kbmax) LOAD_KV(kb + 2, st);
        CP_COMMIT();
    }
#undef LOAD_KV

    // epilogue: write split-A ctx rows (stride 2048) for the Wo GEMM
    const int b = bh >> 4, h = bh & 15;
    const int r0 = q0 + w * 16 + (lane >> 2);
    const int dc = 2 * (lane & 3);
    #pragma unroll
    for (int half = 0; half < 2; half++) {
        const int q = r0 + 8 * half;
        const float lv  = (half == 0) ? l0 : l1;
        const float inv = (q == 0) ? 0.f : (1.f / lv);
        const size_t rowb = ((size_t)b * SEQ + q) * 2048;
        #pragma unroll
        for (int nt = 0; nt < 8; nt++) {
            const float x = O[nt][half * 2 + 0] * inv;
            const float y = O[nt][half * 2 + 1] * inv;
            const int col = h * 64 + nt * 8 + dc;
            uint32_t hi, lo;
            split_pack(x, y, hi, lo);
            *(uint32_t*)&Actx[rowb + col]        = hi;
            *(uint32_t*)&Actx[rowb + 1024 + col] = lo;
        }
    }
}

// ---------------- layernorm (optional split-A side output, stride 2048) ----------------
__global__ __launch_bounds__(256)
void ln_kernel(const float* __restrict__ X, const float* __restrict__ G,
               const float* __restrict__ Bt, float* __restrict__ O,
               __nv_bfloat16* __restrict__ SP)
{
    __shared__ float ws[8], ws2[8];
    __shared__ float s_mu, s_rs;
    const int t = threadIdx.x;
    const size_t row = blockIdx.x;

    float4 v = *(const float4*)&X[row * D_MODEL + t * 4];
    float s  = v.x + v.y + v.z + v.w;
    float s2 = v.x * v.x + v.y * v.y + v.z * v.z + v.w * v.w;
    #pragma unroll
    for (int o = 16; o; o >>= 1) {
        s  += __shfl_xor_sync(0xffffffffu, s,  o);
        s2 += __shfl_xor_sync(0xffffffffu, s2, o);
    }
    if ((t & 31) == 0) { ws[t >> 5] = s; ws2[t >> 5] = s2; }
    __syncthreads();
    if (t == 0) {
        float S = 0.f, S2 = 0.f;
        #pragma unroll
        for (int w = 0; w < 8; w++) { S += ws[w]; S2 += ws2[w]; }
        const float mu  = S * (1.f / (float)D_MODEL);
        const float var = S2 * (1.f / (float)D_MODEL) - mu * mu;
        s_mu = mu;
        s_rs = rsqrtf(var + 1e-5f);
    }
    __syncthreads();
    const float mu = s_mu, rs = s_rs;

    float4 g = *(const float4*)&G[t * 4];
    float4 b = *(const float4*)&Bt[t * 4];
    float4 r;
    r.x = (v.x - mu) * rs * g.x + b.x;
    r.y = (v.y - mu) * rs * g.y + b.y;
    r.z = (v.z - mu) * rs * g.z + b.z;
    r.w = (v.w - mu) * rs * g.w + b.w;
    *(float4*)&O[row * D_MODEL + t * 4] = r;

    if (SP) {
        uint32_t h0, l0_, h1, l1_;
        split_pack(r.x, r.y, h0, l0_);
        split_pack(r.z, r.w, h1, l1_);
        const size_t base = row * 2048 + t * 4;
        *(uint2*)&SP[base]        = make_uint2(h0, h1);
        *(uint2*)&SP[base + 1024] = make_uint2(l0_, l1_);
    }
}

// ---------------- orchestration ----------------
extern "C" void kernel_launch(void* const* d_in, const int* in_sizes, int n_in,
                              void* d_out, int out_size)
{
    (void)in_sizes; (void)n_in; (void)out_size;

    const float* query = (const float*)d_in[0];
    const float* key_i = (const float*)d_in[1];
    const float* vals  = (const float*)d_in[2];
    const float* Wq = (const float*)d_in[3];
    const float* bq = (const float*)d_in[4];
    const float* Wk = (const float*)d_in[5];
    const float* bk = (const float*)d_in[6];
    const float* Wv = (const float*)d_in[7];
    const float* bv = (const float*)d_in[8];
    const float* Wo = (const float*)d_in[9];
    const float* bo = (const float*)d_in[10];
    const float* ln1g = (const float*)d_in[11];
    const float* ln1b = (const float*)d_in[12];
    const float* W1 = (const float*)d_in[13];
    const float* b1 = (const float*)d_in[14];
    const float* W2 = (const float*)d_in[15];
    const float* b2 = (const float*)d_in[16];
    const float* ln2g = (const float*)d_in[17];
    const float* ln2b = (const float*)d_in[18];
    float* out = (float*)d_out;

    float *pt, *px;
    __nv_bfloat16 *pqh, *pql, *pkh, *pkl, *pvh, *pvl, *pab, *phb, *pwb;
    cudaGetSymbolAddress((void**)&pt,  g_t);
    cudaGetSymbolAddress((void**)&px,  g_x);
    cudaGetSymbolAddress((void**)&pqh, g_qh);
    cudaGetSymbolAddress((void**)&pql, g_ql);
    cudaGetSymbolAddress((void**)&pkh, g_kh);
    cudaGetSymbolAddress((void**)&pkl, g_kl);
    cudaGetSymbolAddress((void**)&pvh, g_vh);
    cudaGetSymbolAddress((void**)&pvl, g_vl);
    cudaGetSymbolAddress((void**)&pab, g_abuf);
    cudaGetSymbolAddress((void**)&phb, g_hbuf);
    cudaGetSymbolAddress((void**)&pwb, g_wbuf);

    cudaFuncSetAttribute(attn_tc,
                         cudaFuncAttributeMaxDynamicSharedMemorySize, ATTN_SMEM);
    cudaFuncSetAttribute(tc_gemm<MODE_QKV>,
                         cudaFuncAttributeMaxDynamicSharedMemorySize, GEMM_SMEM);
    cudaFuncSetAttribute(tc_gemm<MODE_RELU>,
                         cudaFuncAttributeMaxDynamicSharedMemorySize, GEMM_SMEM);
    cudaFuncSetAttribute(tc_gemm<MODE_RES>,
                         cudaFuncAttributeMaxDynamicSharedMemorySize, GEMM_SMEM);

    const dim3 blk(512);
    const dim3 grid_1k(D_MODEL / 128, M_TOT / 256);   // (8, 16)
    const dim3 grid_4k(D_FF / 128,    M_TOT / 256);   // (32, 16)
    const int total4_1k = M_TOT * D_MODEL / 4;

    // ---- QKV projections -> split bf16 [B,H,S,64] hi/lo (Q pre-scaled by 1/8) ----
    act_split_kernel<<<(total4_1k + 255) / 256, 256>>>(query, pab, D_MODEL, total4_1k);
    wt_split_kernel<<<dim3(D_MODEL / 32, D_MODEL / 32), 256>>>(Wq, pwb, D_MODEL, D_MODEL);
    tc_gemm<MODE_QKV><<<grid_1k, blk, GEMM_SMEM>>>(pab, pwb, bq, nullptr, nullptr,
                                                   pqh, pql, 0.125f, D_MODEL, D_MODEL);
    act_split_kernel<<<(total4_1k + 255) / 256, 256>>>(key_i, pab, D_MODEL, total4_1k);
    wt_split_kernel<<<dim3(D_MODEL / 32, D_MODEL / 32), 256>>>(Wk, pwb, D_MODEL, D_MODEL);
    tc_gemm<MODE_QKV><<<grid_1k, blk, GEMM_SMEM>>>(pab, pwb, bk, nullptr, nullptr,
                                                   pkh, pkl, 1.0f, D_MODEL, D_MODEL);
    act_split_kernel<<<(total4_1k + 255) / 256, 256>>>(vals, pab, D_MODEL, total4_1k);
    wt_split_kernel<<<dim3(D_MODEL / 32, D_MODEL / 32), 256>>>(Wv, pwb, D_MODEL, D_MODEL);
    tc_gemm<MODE_QKV><<<grid_1k, blk, GEMM_SMEM>>>(pab, pwb, bv, nullptr, nullptr,
                                                   pvh, pvl, 1.0f, D_MODEL, D_MODEL);

    // ---- tensor-core causal flash attention -> split ctx in g_abuf ----
    attn_tc<<<dim3(SEQ / 128, NB * NH), dim3(256), ATTN_SMEM>>>(pqh, pql, pkh, pkl, pvh, pvl, pab);

    // ---- Wo + residual(query) -> g_t ; LN1 -> g_x (fp32) + split in g_abuf ----
    wt_split_kernel<<<dim3(D_MODEL / 32, D_MODEL / 32), 256>>>(Wo, pwb, D_MODEL, D_MODEL);
    tc_gemm<MODE_RES><<<grid_1k, blk, GEMM_SMEM>>>(pab, pwb, bo, query, pt,
                                                   nullptr, nullptr, 1.0f, D_MODEL, D_MODEL);
    ln_kernel<<<M_TOT, 256>>>(pt, ln1g, ln1b, px, pab);

    // ---- FFN1: relu(x@W1+b1) -> split in g_hbuf ----
    wt_split_kernel<<<dim3(D_MODEL / 32, D_FF / 32), 256>>>(W1, pwb, D_MODEL, D_FF);
    tc_gemm<MODE_RELU><<<grid_4k, blk, GEMM_SMEM>>>(pab, pwb, b1, nullptr, nullptr,
                                                    phb, nullptr, 1.0f, D_FF, D_MODEL);

    // ---- FFN2 + residual(x) -> g_t ; LN2 -> out ----
    wt_split_kernel<<<dim3(D_FF / 32, D_MODEL / 32), 256>>>(W2, pwb, D_FF, D_MODEL);
    tc_gemm<MODE_RES><<<grid_1k, blk, GEMM_SMEM>>>(phb, pwb, b2, px, pt,
                                                   nullptr, nullptr, 1.0f, D_MODEL, D_FF);
    ln_kernel<<<M_TOT, 256>>>(pt, ln2g, ln2b, out, nullptr);
}

// round 16
// speedup vs baseline: 1.8696x; 1.3498x over previous
#include <cuda_runtime.h>
#include <cuda_fp16.h>
#include <cstdint>
#include <math.h>

// ---------------- problem constants ----------------
#define D_MODEL 1024
#define D_FF    4096
#define NB      2
#define SEQ     2048
#define NH      16
#define DK      64
#define M_TOT   (NB*SEQ)          // 4096 rows

enum { MODE_QKV = 1, MODE_RELU = 2, MODE_RES = 3 };

// ---------------- scratch (static device arrays; no allocations) ----------------
__device__ float g_t  [M_TOT * D_MODEL];   // residual sums
__device__ float g_x  [M_TOT * D_MODEL];   // LN1 output (fp32, FFN2 residual)
__device__ __align__(128) __half g_qh[M_TOT * D_MODEL];  // [B,H,S,64] hi (pre-scaled)
__device__ __align__(128) __half g_ql[M_TOT * D_MODEL];  // Q lo plane
__device__ __align__(128) __half g_kh[M_TOT * D_MODEL];  // K hi only
__device__ __align__(128) __half g_vh[M_TOT * D_MODEL];  // V hi only
__device__ __align__(128) __half g_abuf[(size_t)M_TOT * 2 * D_MODEL];  // A [M,2048]
__device__ __align__(128) __half g_hbuf[(size_t)M_TOT * 2 * D_FF];     // A [M,8192]
__device__ __align__(128) __half g_wbuf[(size_t)D_FF * D_MODEL];       // B hi [N,K]

// ================= PTX helpers (baseline ISA: sm_80 features only) =================
__device__ __forceinline__ uint32_t smem_u32(const void* p) {
    uint32_t a;
    asm("{ .reg .u64 t; cvta.to.shared.u64 t, %1; cvt.u32.u64 %0, t; }" : "=r"(a) : "l"(p));
    return a;
}
__device__ __forceinline__ void cp_async16(uint32_t sdst, const void* gsrc) {
    asm volatile("cp.async.cg.shared.global [%0], [%1], 16;" :: "r"(sdst), "l"(gsrc));
}
#define CP_COMMIT() asm volatile("cp.async.commit_group;" ::: "memory")
#define CP_WAIT1()  asm volatile("cp.async.wait_group 1;" ::: "memory")

#define SMEM_SWIZZLE_128B(off) ((off) ^ (((off) >> 3) & 0x70))

#define LDSM_X4(r, addr)                                                        \
    asm volatile("ldmatrix.sync.aligned.m8n8.x4.shared.b16 {%0,%1,%2,%3}, [%4];" \
                 : "=r"((r)[0]), "=r"((r)[1]), "=r"((r)[2]), "=r"((r)[3])        \
                 : "r"(addr))
#define LDSM_X4_T(r, addr)                                                            \
    asm volatile("ldmatrix.sync.aligned.m8n8.x4.trans.shared.b16 {%0,%1,%2,%3}, [%4];" \
                 : "=r"((r)[0]), "=r"((r)[1]), "=r"((r)[2]), "=r"((r)[3])              \
                 : "r"(addr))

__device__ __forceinline__ void mma_f16(float* c, const uint32_t* a,
                                        uint32_t b0, uint32_t b1) {
    asm volatile("mma.sync.aligned.m16n8k16.row.col.f32.f16.f16.f32 "
                 "{%0,%1,%2,%3}, {%4,%5,%6,%7}, {%8,%9}, {%0,%1,%2,%3};"
                 : "+f"(c[0]), "+f"(c[1]), "+f"(c[2]), "+f"(c[3])
                 : "r"(a[0]), "r"(a[1]), "r"(a[2]), "r"(a[3]), "r"(b0), "r"(b1));
}

__device__ __forceinline__ uint32_t pack_h16(float x, float y) {
    __half a = __float2half_rn(x), b = __float2half_rn(y);
    return (uint32_t)__half_as_ushort(a) | ((uint32_t)__half_as_ushort(b) << 16);
}
// hi = h(x),h(y) packed; lo = residuals packed
__device__ __forceinline__ void split_pack(float x, float y, uint32_t& hi, uint32_t& lo) {
    __half hx = __float2half_rn(x), hy = __float2half_rn(y);
    hi = (uint32_t)__half_as_ushort(hx) | ((uint32_t)__half_as_ushort(hy) << 16);
    lo = pack_h16(x - __half2float(hx), y - __half2float(hy));
}

// ================= split-precision conversion kernels =================
// A row = [A_hi | A_lo]  (M x 2K), fp16
__global__ __launch_bounds__(256)
void act_split_kernel(const float* __restrict__ X, __half* __restrict__ Y,
                      int K, int total4)
{
    int i = blockIdx.x * 256 + threadIdx.x;
    if (i >= total4) return;
    int idx = i << 2;
    float4 v = *(const float4*)&X[idx];
    int m = idx / K, k = idx - m * K;
    uint32_t h0, l0, h1, l1;
    split_pack(v.x, v.y, h0, l0);
    split_pack(v.z, v.w, h1, l1);
    size_t base = (size_t)m * 2 * K + k;
    *(uint2*)&Y[base]     = make_uint2(h0, h1);
    *(uint2*)&Y[base + K] = make_uint2(l0, l1);
}

// W [K,N] fp32 -> Y [N,K] fp16 hi only, transposed
__global__ __launch_bounds__(256)
void wt_split_kernel(const float* __restrict__ W, __half* __restrict__ Y,
                     int K, int N)
{
    __shared__ float tile[32][33];
    const int tx = threadIdx.x & 31, ty = threadIdx.x >> 5;
    const int k0 = blockIdx.x * 32, n0 = blockIdx.y * 32;
    #pragma unroll
    for (int u = 0; u < 4; u++)
        tile[ty + 8 * u][tx] = W[(size_t)(k0 + ty + 8 * u) * N + n0 + tx];
    __syncthreads();
    #pragma unroll
    for (int u = 0; u < 4; u++) {
        const int n = n0 + ty + 8 * u;
        Y[(size_t)n * K + (k0 + tx)] = __float2half_rn(tile[tx][ty + 8 * u]);
    }
}

// ================= HMMA fp16 GEMM: C = (A_hi + A_lo) @ B_hi^T  (2 passes) =================
// 256x128 CTA tile, 512 threads (16 warps, 4x4 of 64x32), K-chunk = 64 real K,
// 2-stage cp.async pipeline; stage holds {a_hi 32K, a_lo 32K, b_hi 16K} = 80 KB.
#define S_AH 0
#define S_AL 32768
#define S_BH 65536
#define STAGE_BYTES 81920
#define GEMM_SMEM   (2 * STAGE_BYTES)   // 163840

template<int MODE>
__global__ __launch_bounds__(512, 1)
void tc_gemm(const __half* __restrict__ A, const __half* __restrict__ Bw,
             const float* __restrict__ bias, const float* __restrict__ Res,
             float* __restrict__ C,
             __half* __restrict__ Oh, __half* __restrict__ Ol,
             float scale, int N, int Kr)
{
    extern __shared__ __align__(1024) char smem[];
    const uint32_t tiles = smem_u32(smem);
    const int t    = threadIdx.x;
    const int lane = t & 31;
    const int wid  = t >> 5;
    const int wm   = wid >> 2;          // 0..3 (64 rows each)
    const int wn   = wid & 3;           // 0..3 (32 cols each)
    const int n0   = blockIdx.x * 128;
    const int m0   = blockIdx.y * 256;
    const size_t rowA = (size_t)2 * Kr * 2;   // bytes per A row (hi|lo)
    const size_t loOf = (size_t)Kr * 2;       // byte offset to A lo plane
    const size_t rowBb = (size_t)Kr * 2;      // bytes per B row (hi only)

#define LOAD_CHUNK(CH, ST) do {                                                        \
    const uint32_t stb = tiles + (ST) * STAGE_BYTES;                                   \
    const size_t kb = (size_t)(CH) * 128;                                              \
    _Pragma("unroll")                                                                  \
    for (int u = 0; u < 4; u++) {                                                      \
        const int idx = t + 512 * u;                                                   \
        const int row = idx >> 3;                                                      \
        const int c8  = (idx & 7) << 4;                                                \
        const uint32_t sw = SMEM_SWIZZLE_128B((uint32_t)(row * 128 + c8));             \
        const char* ap = (const char*)A + (size_t)(m0 + row) * rowA + kb + c8;         \
        cp_async16(stb + S_AH + sw, ap);                                               \
        cp_async16(stb + S_AL + sw, ap + loOf);                                        \
    }                                                                                  \
    _Pragma("unroll")                                                                  \
    for (int u = 0; u < 2; u++) {                                                      \
        const int idx = t + 512 * u;                                                   \
        const int row = idx >> 3;                                                      \
        const int c8  = (idx & 7) << 4;                                                \
        const uint32_t sw = SMEM_SWIZZLE_128B((uint32_t)(row * 128 + c8));             \
        cp_async16(stb + S_BH + sw,                                                    \
                   (const char*)Bw + (size_t)(n0 + row) * rowBb + kb + c8);            \
    }                                                                                  \
    CP_COMMIT();                                                                       \
} while (0)

    const int nch = Kr >> 6;
    LOAD_CHUNK(0, 0);
    LOAD_CHUNK(1, 1);

    float acc[4][4][4];
    #pragma unroll
    for (int mt = 0; mt < 4; mt++)
        #pragma unroll
        for (int nt = 0; nt < 4; nt++)
            #pragma unroll
            for (int r = 0; r < 4; r++) acc[mt][nt][r] = 0.f;

    const int a_row = wm * 64 + (lane & 15);
    const int a_kb  = (lane >> 4) << 4;
    const int b_row = wn * 32 + (lane & 7) + ((lane >> 4) << 3);
    const int b_kb  = ((lane >> 3) & 1) << 4;

    #pragma unroll 1
    for (int c = 0; c < nch; c++) {
        const int st = c & 1;
        CP_WAIT1();
        __syncthreads();
        const uint32_t stb = tiles + st * STAGE_BYTES;

        #pragma unroll
        for (int ks = 0; ks < 4; ks++) {
            uint32_t ah[4][4], al[4][4];
            #pragma unroll
            for (int mt = 0; mt < 4; mt++) {
                const uint32_t off = SMEM_SWIZZLE_128B(
                    (uint32_t)((a_row + mt * 16) * 128 + ks * 32 + a_kb));
                LDSM_X4(ah[mt], stb + S_AH + off);
                LDSM_X4(al[mt], stb + S_AL + off);
            }
            uint32_t bh[2][4];
            #pragma unroll
            for (int nt2 = 0; nt2 < 2; nt2++) {
                const uint32_t off = SMEM_SWIZZLE_128B(
                    (uint32_t)((b_row + nt2 * 16) * 128 + ks * 32 + b_kb));
                LDSM_X4(bh[nt2], stb + S_BH + off);
            }
            #pragma unroll
            for (int mt = 0; mt < 4; mt++)
                #pragma unroll
                for (int nt = 0; nt < 4; nt++)
                    mma_f16(acc[mt][nt], ah[mt],
                            bh[nt >> 1][(nt & 1) * 2], bh[nt >> 1][(nt & 1) * 2 + 1]);
            #pragma unroll
            for (int mt = 0; mt < 4; mt++)
                #pragma unroll
                for (int nt = 0; nt < 4; nt++)
                    mma_f16(acc[mt][nt], al[mt],
                            bh[nt >> 1][(nt & 1) * 2], bh[nt >> 1][(nt & 1) * 2 + 1]);
        }

        __syncthreads();
        if (c + 2 < nch) LOAD_CHUNK(c + 2, st);
        else             CP_COMMIT();
    }
#undef LOAD_CHUNK

    // ---------------- epilogue ----------------
    const int qr = lane >> 2;
    const int qc = (lane & 3) << 1;
    #pragma unroll
    for (int mt = 0; mt < 4; mt++) {
        #pragma unroll
        for (int nt = 0; nt < 4; nt++) {
            const int col = n0 + wn * 32 + nt * 8 + qc;
            const float2 bv = *(const float2*)&bias[col];
            #pragma unroll
            for (int half = 0; half < 2; half++) {
                const int row = m0 + wm * 64 + mt * 16 + qr + half * 8;
                float rx = acc[mt][nt][half * 2 + 0] + bv.x;
                float ry = acc[mt][nt][half * 2 + 1] + bv.y;
                if (MODE == MODE_QKV) {
                    rx *= scale; ry *= scale;
                    uint32_t hi, lo;
                    split_pack(rx, ry, hi, lo);
                    const int h = col >> 6, d = col & 63;
                    const int bb = row >> 11, ss = row & 2047;
                    const size_t o = ((size_t)(bb * NH + h) * SEQ + ss) * DK + d;
                    *(uint32_t*)&Oh[o] = hi;
                    if (Ol) *(uint32_t*)&Ol[o] = lo;
                } else if (MODE == MODE_RELU) {
                    rx = fmaxf(rx, 0.f); ry = fmaxf(ry, 0.f);
                    uint32_t hi, lo;
                    split_pack(rx, ry, hi, lo);
                    const size_t base = (size_t)row * 2 * N;
                    *(uint32_t*)&Oh[base + col]     = hi;
                    *(uint32_t*)&Oh[base + N + col] = lo;
                } else { // MODE_RES
                    float2 rv = *(const float2*)&Res[(size_t)row * N + col];
                    float2 r = make_float2(rx + rv.x, ry + rv.y);
                    *(float2*)&C[(size_t)row * N + col] = r;
                }
            }
        }
    }
}

// ================= tensor-core flash attention (fp16 2-pass) =================
// CTA: 128 queries x 64-key blocks, 8 warps (16 q-rows each).
// S = Qh*Kh + Ql*Kh ; O += Ph*Vh + Pl*Vh (P split from accumulators).
#define SQH  0
#define SQL  16384
#define SKV0 32768
#define KV_STAGE 16384           // kh 0, vh 8192
#define ATTN_SMEM 65536

__global__ __launch_bounds__(256, 2)
void attn_tc(const __half* __restrict__ Qh, const __half* __restrict__ Ql,
             const __half* __restrict__ Kh, const __half* __restrict__ Vh,
             __half* __restrict__ Actx)   // split A rows, stride 2048
{
    extern __shared__ __align__(1024) char smem[];
    const uint32_t sb = smem_u32(smem);
    const int t = threadIdx.x, lane = t & 31, w = t >> 5;
    const int qt = gridDim.x - 1 - blockIdx.x;
    const int bh = blockIdx.y;
    const int q0 = qt * 128;

    const char* qhB = (const char*)(Qh + ((size_t)bh * SEQ + q0) * DK);
    const char* qlB = (const char*)(Ql + ((size_t)bh * SEQ + q0) * DK);
    const char* khB = (const char*)(Kh + (size_t)bh * SEQ * DK);
    const char* vhB = (const char*)(Vh + (size_t)bh * SEQ * DK);

#define LOAD_KV(KB_, ST_) do {                                                   \
    const uint32_t stb = sb + SKV0 + (ST_) * KV_STAGE;                           \
    _Pragma("unroll")                                                            \
    for (int u = 0; u < 2; u++) {                                                \
        const int idx = t + 256 * u;                                             \
        const int row = idx >> 3;                                                \
        const int c8  = (idx & 7) << 4;                                          \
        const uint32_t sw = SMEM_SWIZZLE_128B((uint32_t)(row * 128 + c8));       \
        const size_t go = (size_t)((KB_) * 64 + row) * 128 + c8;                 \
        cp_async16(stb + sw,        khB + go);                                   \
        cp_async16(stb + 8192 + sw, vhB + go);                                   \
    }                                                                            \
} while (0)

    #pragma unroll
    for (int u = 0; u < 4; u++) {
        const int idx = t + 256 * u;
        const int row = idx >> 3;
        const int c8  = (idx & 7) << 4;
        const uint32_t sw = SMEM_SWIZZLE_128B((uint32_t)(row * 128 + c8));
        cp_async16(sb + SQH + sw, qhB + (size_t)row * 128 + c8);
        cp_async16(sb + SQL + sw, qlB + (size_t)row * 128 + c8);
    }
    LOAD_KV(0, 0);
    CP_COMMIT();
    LOAD_KV(1, 1);
    CP_COMMIT();

    const int kbmax = (q0 + 126) >> 6;

    float O[8][4];
    #pragma unroll
    for (int nt = 0; nt < 8; nt++)
        #pragma unroll
        for (int j = 0; j < 4; j++) O[nt][j] = 0.f;
    float m0 = -1e30f, m1 = -1e30f, l0 = 0.f, l1 = 0.f;

    const int a_row = w * 16 + (lane & 15);
    const int a_kb  = (lane >> 4) << 4;
    const int bk_row = (lane & 7) + ((lane >> 4) << 3);
    const int bk_kb  = ((lane >> 3) & 1) << 4;
    const int v_row  = ((lane >> 3) & 1) * 8 + (lane & 7);
    const int v_cb   = (lane >> 4) << 4;

    #pragma unroll 1
    for (int kb = 0; kb <= kbmax; kb++) {
        const int st = kb & 1;
        CP_WAIT1();
        __syncthreads();
        const uint32_t KVB = sb + SKV0 + st * KV_STAGE;

        float sc[8][4];
        #pragma unroll
        for (int nt = 0; nt < 8; nt++)
            #pragma unroll
            for (int j = 0; j < 4; j++) sc[nt][j] = 0.f;

#define QK_PASS(QOFF) do {                                                            \
    _Pragma("unroll")                                                                 \
    for (int ks = 0; ks < 4; ks++) {                                                  \
        uint32_t a[4];                                                                \
        LDSM_X4(a, sb + (QOFF) + SMEM_SWIZZLE_128B(                                   \
            (uint32_t)(a_row * 128 + ks * 32 + a_kb)));                               \
        uint32_t bq[4][4];                                                            \
        _Pragma("unroll")                                                             \
        for (int nt2 = 0; nt2 < 4; nt2++)                                             \
            LDSM_X4(bq[nt2], KVB + SMEM_SWIZZLE_128B(                                 \
                (uint32_t)((nt2 * 16 + bk_row) * 128 + ks * 32 + bk_kb)));            \
        _Pragma("unroll")                                                             \
        for (int nt = 0; nt < 8; nt++)                                                \
            mma_f16(sc[nt], a, bq[nt >> 1][(nt & 1) * 2], bq[nt >> 1][(nt & 1) * 2 + 1]); \
    }                                                                                 \
} while (0)

        QK_PASS(SQH);
        QK_PASS(SQL);
#undef QK_PASS

        if (kb >= 2 * qt) {
            const int cb0  = kb * 64 + 2 * (lane & 3);
            const int row0 = q0 + w * 16 + (lane >> 2);
            #pragma unroll
            for (int nt = 0; nt < 8; nt++) {
                const int cbase = cb0 + nt * 8;
                if (cbase + 0 >= row0)     sc[nt][0] = -1e30f;
                if (cbase + 1 >= row0)     sc[nt][1] = -1e30f;
                if (cbase + 0 >= row0 + 8) sc[nt][2] = -1e30f;
                if (cbase + 1 >= row0 + 8) sc[nt][3] = -1e30f;
            }
        }

        float mx0 = -1e30f, mx1 = -1e30f;
        #pragma unroll
        for (int nt = 0; nt < 8; nt++) {
            mx0 = fmaxf(mx0, fmaxf(sc[nt][0], sc[nt][1]));
            mx1 = fmaxf(mx1, fmaxf(sc[nt][2], sc[nt][3]));
        }
        #pragma unroll
        for (int o = 1; o <= 2; o <<= 1) {
            mx0 = fmaxf(mx0, __shfl_xor_sync(0xffffffffu, mx0, o));
            mx1 = fmaxf(mx1, __shfl_xor_sync(0xffffffffu, mx1, o));
        }
        const float mn0 = fmaxf(m0, mx0), mn1 = fmaxf(m1, mx1);
        const float c0 = __expf(m0 - mn0), c1 = __expf(m1 - mn1);
        m0 = mn0; m1 = mn1;
        float rs0 = 0.f, rs1 = 0.f;
        #pragma unroll
        for (int nt = 0; nt < 8; nt++) {
            sc[nt][0] = __expf(sc[nt][0] - mn0);
            sc[nt][1] = __expf(sc[nt][1] - mn0);
            sc[nt][2] = __expf(sc[nt][2] - mn1);
            sc[nt][3] = __expf(sc[nt][3] - mn1);
            rs0 += sc[nt][0] + sc[nt][1];
            rs1 += sc[nt][2] + sc[nt][3];
        }
        #pragma unroll
        for (int o = 1; o <= 2; o <<= 1) {
            rs0 += __shfl_xor_sync(0xffffffffu, rs0, o);
            rs1 += __shfl_xor_sync(0xffffffffu, rs1, o);
        }
        l0 = l0 * c0 + rs0;
        l1 = l1 * c1 + rs1;
        #pragma unroll
        for (int nt = 0; nt < 8; nt++) {
            O[nt][0] *= c0; O[nt][1] *= c0;
            O[nt][2] *= c1; O[nt][3] *= c1;
        }

        // PV: O += (Ph + Pl) * Vh
        #pragma unroll
        for (int kk = 0; kk < 4; kk++) {
            uint32_t ah[4], al[4];
            split_pack(sc[2*kk][0],   sc[2*kk][1],   ah[0], al[0]);
            split_pack(sc[2*kk][2],   sc[2*kk][3],   ah[1], al[1]);
            split_pack(sc[2*kk+1][0], sc[2*kk+1][1], ah[2], al[2]);
            split_pack(sc[2*kk+1][2], sc[2*kk+1][3], ah[3], al[3]);
            #pragma unroll
            for (int nt2 = 0; nt2 < 4; nt2++) {
                const uint32_t vaddr = SMEM_SWIZZLE_128B(
                    (uint32_t)((kk * 16 + v_row) * 128 + nt2 * 32 + v_cb));
                uint32_t bv[4];
                LDSM_X4_T(bv, KVB + 8192 + vaddr);
                mma_f16(O[2*nt2],   ah, bv[0], bv[1]);
                mma_f16(O[2*nt2+1], ah, bv[2], bv[3]);
                mma_f16(O[2*nt2],   al, bv[0], bv[1]);
                mma_f16(O[2*nt2+1], al, bv[2], bv[3]);
            }
        }

        __syncthreads();
        if (kb + 2 <= kbmax) LOAD_KV(kb + 2, st);
        CP_COMMIT();
    }
#undef LOAD_KV

    // epilogue: write split-A ctx rows (stride 2048) for the Wo GEMM
    const int b = bh >> 4, h = bh & 15;
    const int r0 = q0 + w * 16 + (lane >> 2);
    const int dc = 2 * (lane & 3);
    #pragma unroll
    for (int half = 0; half < 2; half++) {
        const int q = r0 + 8 * half;
        const float lv  = (half == 0) ? l0 : l1;
        const float inv = (q == 0) ? 0.f : (1.f / lv);
        const size_t rowb = ((size_t)b * SEQ + q) * 2048;
        #pragma unroll
        for (int nt = 0; nt < 8; nt++) {
            const float x = O[nt][half * 2 + 0] * inv;
            const float y = O[nt][half * 2 + 1] * inv;
            const int col = h * 64 + nt * 8 + dc;
            uint32_t hi, lo;
            split_pack(x, y, hi, lo);
            *(uint32_t*)&Actx[rowb + col]        = hi;
            *(uint32_t*)&Actx[rowb + 1024 + col] = lo;
        }
    }
}

// ---------------- layernorm (optional split-A side output, stride 2048) ----------------
__global__ __launch_bounds__(256)
void ln_kernel(const float* __restrict__ X, const float* __restrict__ G,
               const float* __restrict__ Bt, float* __restrict__ O,
               __half* __restrict__ SP)
{
    __shared__ float ws[8], ws2[8];
    __shared__ float s_mu, s_rs;
    const int t = threadIdx.x;
    const size_t row = blockIdx.x;

    float4 v = *(const float4*)&X[row * D_MODEL + t * 4];
    float s  = v.x + v.y + v.z + v.w;
    float s2 = v.x * v.x + v.y * v.y + v.z * v.z + v.w * v.w;
    #pragma unroll
    for (int o = 16; o; o >>= 1) {
        s  += __shfl_xor_sync(0xffffffffu, s,  o);
        s2 += __shfl_xor_sync(0xffffffffu, s2, o);
    }
    if ((t & 31) == 0) { ws[t >> 5] = s; ws2[t >> 5] = s2; }
    __syncthreads();
    if (t == 0) {
        float S = 0.f, S2 = 0.f;
        #pragma unroll
        for (int w = 0; w < 8; w++) { S += ws[w]; S2 += ws2[w]; }
        const float mu  = S * (1.f / (float)D_MODEL);
        const float var = S2 * (1.f / (float)D_MODEL) - mu * mu;
        s_mu = mu;
        s_rs = rsqrtf(var + 1e-5f);
    }
    __syncthreads();
    const float mu = s_mu, rs = s_rs;

    float4 g = *(const float4*)&G[t * 4];
    float4 b = *(const float4*)&Bt[t * 4];
    float4 r;
    r.x = (v.x - mu) * rs * g.x + b.x;
    r.y = (v.y - mu) * rs * g.y + b.y;
    r.z = (v.z - mu) * rs * g.z + b.z;
    r.w = (v.w - mu) * rs * g.w + b.w;
    *(float4*)&O[row * D_MODEL + t * 4] = r;

    if (SP) {
        uint32_t h0, l0_, h1, l1_;
        split_pack(r.x, r.y, h0, l0_);
        split_pack(r.z, r.w, h1, l1_);
        const size_t base = row * 2048 + t * 4;
        *(uint2*)&SP[base]        = make_uint2(h0, h1);
        *(uint2*)&SP[base + 1024] = make_uint2(l0_, l1_);
    }
}

// ---------------- orchestration ----------------
extern "C" void kernel_launch(void* const* d_in, const int* in_sizes, int n_in,
                              void* d_out, int out_size)
{
    (void)in_sizes; (void)n_in; (void)out_size;

    const float* query = (const float*)d_in[0];
    const float* key_i = (const float*)d_in[1];
    const float* vals  = (const float*)d_in[2];
    const float* Wq = (const float*)d_in[3];
    const float* bq = (const float*)d_in[4];
    const float* Wk = (const float*)d_in[5];
    const float* bk = (const float*)d_in[6];
    const float* Wv = (const float*)d_in[7];
    const float* bv = (const float*)d_in[8];
    const float* Wo = (const float*)d_in[9];
    const float* bo = (const float*)d_in[10];
    const float* ln1g = (const float*)d_in[11];
    const float* ln1b = (const float*)d_in[12];
    const float* W1 = (const float*)d_in[13];
    const float* b1 = (const float*)d_in[14];
    const float* W2 = (const float*)d_in[15];
    const float* b2 = (const float*)d_in[16];
    const float* ln2g = (const float*)d_in[17];
    const float* ln2b = (const float*)d_in[18];
    float* out = (float*)d_out;

    float *pt, *px;
    __half *pqh, *pql, *pkh, *pvh, *pab, *phb, *pwb;
    cudaGetSymbolAddress((void**)&pt,  g_t);
    cudaGetSymbolAddress((void**)&px,  g_x);
    cudaGetSymbolAddress((void**)&pqh, g_qh);
    cudaGetSymbolAddress((void**)&pql, g_ql);
    cudaGetSymbolAddress((void**)&pkh, g_kh);
    cudaGetSymbolAddress((void**)&pvh, g_vh);
    cudaGetSymbolAddress((void**)&pab, g_abuf);
    cudaGetSymbolAddress((void**)&phb, g_hbuf);
    cudaGetSymbolAddress((void**)&pwb, g_wbuf);

    cudaFuncSetAttribute(attn_tc,
                         cudaFuncAttributeMaxDynamicSharedMemorySize, ATTN_SMEM);
    cudaFuncSetAttribute(tc_gemm<MODE_QKV>,
                         cudaFuncAttributeMaxDynamicSharedMemorySize, GEMM_SMEM);
    cudaFuncSetAttribute(tc_gemm<MODE_RELU>,
                         cudaFuncAttributeMaxDynamicSharedMemorySize, GEMM_SMEM);
    cudaFuncSetAttribute(tc_gemm<MODE_RES>,
                         cudaFuncAttributeMaxDynamicSharedMemorySize, GEMM_SMEM);

    const dim3 blk(512);
    const dim3 grid_1k(D_MODEL / 128, M_TOT / 256);   // (8, 16)
    const dim3 grid_4k(D_FF / 128,    M_TOT / 256);   // (32, 16)
    const int total4_1k = M_TOT * D_MODEL / 4;

    // ---- QKV projections -> fp16 [B,H,S,64] (Q: hi+lo pre-scaled; K,V: hi) ----
    act_split_kernel<<<(total4_1k + 255) / 256, 256>>>(query, pab, D_MODEL, total4_1k);
    wt_split_kernel<<<dim3(D_MODEL / 32, D_MODEL / 32), 256>>>(Wq, pwb, D_MODEL, D_MODEL);
    tc_gemm<MODE_QKV><<<grid_1k, blk, GEMM_SMEM>>>(pab, pwb, bq, nullptr, nullptr,
                                                   pqh, pql, 0.125f, D_MODEL, D_MODEL);
    act_split_kernel<<<(total4_1k + 255) / 256, 256>>>(key_i, pab, D_MODEL, total4_1k);
    wt_split_kernel<<<dim3(D_MODEL / 32, D_MODEL / 32), 256>>>(Wk, pwb, D_MODEL, D_MODEL);
    tc_gemm<MODE_QKV><<<grid_1k, blk, GEMM_SMEM>>>(pab, pwb, bk, nullptr, nullptr,
                                                   pkh, nullptr, 1.0f, D_MODEL, D_MODEL);
    act_split_kernel<<<(total4_1k + 255) / 256, 256>>>(vals, pab, D_MODEL, total4_1k);
    wt_split_kernel<<<dim3(D_MODEL / 32, D_MODEL / 32), 256>>>(Wv, pwb, D_MODEL, D_MODEL);
    tc_gemm<MODE_QKV><<<grid_1k, blk, GEMM_SMEM>>>(pab, pwb, bv, nullptr, nullptr,
                                                   pvh, nullptr, 1.0f, D_MODEL, D_MODEL);

    // ---- tensor-core causal flash attention -> split ctx in g_abuf ----
    attn_tc<<<dim3(SEQ / 128, NB * NH), dim3(256), ATTN_SMEM>>>(pqh, pql, pkh, pvh, pab);

    // ---- Wo + residual(query) -> g_t ; LN1 -> g_x (fp32) + split in g_abuf ----
    wt_split_kernel<<<dim3(D_MODEL / 32, D_MODEL / 32), 256>>>(Wo, pwb, D_MODEL, D_MODEL);
    tc_gemm<MODE_RES><<<grid_1k, blk, GEMM_SMEM>>>(pab, pwb, bo, query, pt,
                                                   nullptr, nullptr, 1.0f, D_MODEL, D_MODEL);
    ln_kernel<<<M_TOT, 256>>>(pt, ln1g, ln1b, px, pab);

    // ---- FFN1: relu(x@W1+b1) -> split in g_hbuf ----
    wt_split_kernel<<<dim3(D_MODEL / 32, D_FF / 32), 256>>>(W1, pwb, D_MODEL, D_FF);
    tc_gemm<MODE_RELU><<<grid_4k, blk, GEMM_SMEM>>>(pab, pwb, b1, nullptr, nullptr,
                                                    phb, nullptr, 1.0f, D_FF, D_MODEL);

    // ---- FFN2 + residual(x) -> g_t ; LN2 -> out ----
    wt_split_kernel<<<dim3(D_FF / 32, D_MODEL / 32), 256>>>(W2, pwb, D_FF, D_MODEL);
    tc_gemm<MODE_RES><<<grid_1k, blk, GEMM_SMEM>>>(phb, pwb, b2, px, pt,
                                                   nullptr, nullptr, 1.0f, D_MODEL, D_FF);
    ln_kernel<<<M_TOT, 256>>>(pt, ln2g, ln2b, out, nullptr);
}

// round 17
// speedup vs baseline: 2.7250x; 1.4575x over previous
#include <cuda_runtime.h>
#include <cuda_fp16.h>
#include <cstdint>
#include <math.h>

// ---------------- problem constants ----------------
#define D_MODEL 1024
#define D_FF    4096
#define NB      2
#define SEQ     2048
#define NH      16
#define DK      64
#define M_TOT   (NB*SEQ)          // 4096 rows

enum { MODE_QKV = 1, MODE_RELU = 2, MODE_RES = 3 };

// ---------------- scratch (static device arrays; no allocations) ----------------
__device__ float g_t  [M_TOT * D_MODEL];   // residual sums
__device__ float g_x  [M_TOT * D_MODEL];   // LN1 output (fp32, FFN2 residual)
__device__ __align__(128) __half g_qh[M_TOT * D_MODEL];  // [B,H,S,64] hi (pre-scaled)
__device__ __align__(128) __half g_kh[M_TOT * D_MODEL];  // K hi
__device__ __align__(128) __half g_vh[M_TOT * D_MODEL];  // V hi
__device__ __align__(128) __half g_abuf[(size_t)M_TOT * 2 * D_MODEL];  // A [M,2048] (split) or [M,1024]
__device__ __align__(128) __half g_hbuf[(size_t)M_TOT * D_FF];         // h hi [M,4096]
__device__ __align__(128) __half g_wbuf[(size_t)D_FF * D_MODEL];       // B hi [N,K]

// ================= PTX helpers (baseline ISA: sm_80 features only) =================
__device__ __forceinline__ uint32_t smem_u32(const void* p) {
    uint32_t a;
    asm("{ .reg .u64 t; cvta.to.shared.u64 t, %1; cvt.u32.u64 %0, t; }" : "=r"(a) : "l"(p));
    return a;
}
__device__ __forceinline__ void cp_async16(uint32_t sdst, const void* gsrc) {
    asm volatile("cp.async.cg.shared.global [%0], [%1], 16;" :: "r"(sdst), "l"(gsrc));
}
#define CP_COMMIT() asm volatile("cp.async.commit_group;" ::: "memory")
#define CP_WAIT1()  asm volatile("cp.async.wait_group 1;" ::: "memory")
#define CP_WAIT2()  asm volatile("cp.async.wait_group 2;" ::: "memory")

#define SMEM_SWIZZLE_128B(off) ((off) ^ (((off) >> 3) & 0x70))

#define LDSM_X4(r, addr)                                                        \
    asm volatile("ldmatrix.sync.aligned.m8n8.x4.shared.b16 {%0,%1,%2,%3}, [%4];" \
                 : "=r"((r)[0]), "=r"((r)[1]), "=r"((r)[2]), "=r"((r)[3])        \
                 : "r"(addr))
#define LDSM_X4_T(r, addr)                                                            \
    asm volatile("ldmatrix.sync.aligned.m8n8.x4.trans.shared.b16 {%0,%1,%2,%3}, [%4];" \
                 : "=r"((r)[0]), "=r"((r)[1]), "=r"((r)[2]), "=r"((r)[3])              \
                 : "r"(addr))

__device__ __forceinline__ void mma_f16(float* c, const uint32_t* a,
                                        uint32_t b0, uint32_t b1) {
    asm volatile("mma.sync.aligned.m16n8k16.row.col.f32.f16.f16.f32 "
                 "{%0,%1,%2,%3}, {%4,%5,%6,%7}, {%8,%9}, {%0,%1,%2,%3};"
                 : "+f"(c[0]), "+f"(c[1]), "+f"(c[2]), "+f"(c[3])
                 : "r"(a[0]), "r"(a[1]), "r"(a[2]), "r"(a[3]), "r"(b0), "r"(b1));
}

__device__ __forceinline__ uint32_t pack_h16(float x, float y) {
    __half a = __float2half_rn(x), b = __float2half_rn(y);
    return (uint32_t)__half_as_ushort(a) | ((uint32_t)__half_as_ushort(b) << 16);
}
__device__ __forceinline__ void split_pack(float x, float y, uint32_t& hi, uint32_t& lo) {
    __half hx = __float2half_rn(x), hy = __float2half_rn(y);
    hi = (uint32_t)__half_as_ushort(hx) | ((uint32_t)__half_as_ushort(hy) << 16);
    lo = pack_h16(x - __half2float(hx), y - __half2float(hy));
}

// ================= split-precision conversion kernels =================
// A row = [A_hi | A_lo]  (M x 2K), fp16
__global__ __launch_bounds__(256)
void act_split_kernel(const float* __restrict__ X, __half* __restrict__ Y,
                      int K, int total4)
{
    int i = blockIdx.x * 256 + threadIdx.x;
    if (i >= total4) return;
    int idx = i << 2;
    float4 v = *(const float4*)&X[idx];
    int m = idx / K, k = idx - m * K;
    uint32_t h0, l0, h1, l1;
    split_pack(v.x, v.y, h0, l0);
    split_pack(v.z, v.w, h1, l1);
    size_t base = (size_t)m * 2 * K + k;
    *(uint2*)&Y[base]     = make_uint2(h0, h1);
    *(uint2*)&Y[base + K] = make_uint2(l0, l1);
}

// W [K,N] fp32 -> Y [N,K] fp16 hi only, transposed
__global__ __launch_bounds__(256)
void wt_split_kernel(const float* __restrict__ W, __half* __restrict__ Y,
                     int K, int N)
{
    __shared__ float tile[32][33];
    const int tx = threadIdx.x & 31, ty = threadIdx.x >> 5;
    const int k0 = blockIdx.x * 32, n0 = blockIdx.y * 32;
    #pragma unroll
    for (int u = 0; u < 4; u++)
        tile[ty + 8 * u][tx] = W[(size_t)(k0 + ty + 8 * u) * N + n0 + tx];
    __syncthreads();
    #pragma unroll
    for (int u = 0; u < 4; u++) {
        const int n = n0 + ty + 8 * u;
        Y[(size_t)n * K + (k0 + tx)] = __float2half_rn(tile[tx][ty + 8 * u]);
    }
}

// ================= HMMA fp16 GEMM =================
// PASSES=2: C = (A_hi + A_lo) @ B_hi^T   (A rows [hi|lo], stride 2K)
// PASSES=1: C = A_hi @ B_hi^T            (A rows hi, stride K)
// 256x128 CTA tile, 512 threads (16 warps, 4x4 of 64x32), K-chunk = 64.
template<int MODE, int PASSES>
__global__ __launch_bounds__(512, 1)
void tc_gemm(const __half* __restrict__ A, const __half* __restrict__ Bw,
             const float* __restrict__ bias, const float* __restrict__ Res,
             float* __restrict__ C,
             __half* __restrict__ Oh,
             float scale, int N, int Kr)
{
    constexpr uint32_t S_AL   = 32768;
    constexpr uint32_t S_BH   = (PASSES == 2) ? 65536u : 32768u;
    constexpr uint32_t STAGE  = (PASSES == 2) ? 81920u : 49152u;
    constexpr int      NST    = (PASSES == 2) ? 2 : 3;

    extern __shared__ __align__(1024) char smem[];
    const uint32_t tiles = smem_u32(smem);
    const int t    = threadIdx.x;
    const int lane = t & 31;
    const int wid  = t >> 5;
    const int wm   = wid >> 2;          // 0..3 (64 rows each)
    const int wn   = wid & 3;           // 0..3 (32 cols each)
    const int n0   = blockIdx.x * 128;
    const int m0   = blockIdx.y * 256;
    const size_t rowA = (size_t)PASSES * Kr * 2;  // bytes per A row
    const size_t loOf = (size_t)Kr * 2;           // A lo plane offset
    const size_t rowBb = (size_t)Kr * 2;          // bytes per B row

#define LOAD_CHUNK(CH, ST) do {                                                        \
    const uint32_t stb = tiles + (uint32_t)(ST) * STAGE;                               \
    const size_t kb = (size_t)(CH) * 128;                                              \
    _Pragma("unroll")                                                                  \
    for (int u = 0; u < 4; u++) {                                                      \
        const int idx = t + 512 * u;                                                   \
        const int row = idx >> 3;                                                      \
        const int c8  = (idx & 7) << 4;                                                \
        const uint32_t sw = SMEM_SWIZZLE_128B((uint32_t)(row * 128 + c8));             \
        const char* ap = (const char*)A + (size_t)(m0 + row) * rowA + kb + c8;         \
        cp_async16(stb + sw, ap);                                                      \
        if (PASSES == 2) cp_async16(stb + S_AL + sw, ap + loOf);                       \
    }                                                                                  \
    _Pragma("unroll")                                                                  \
    for (int u = 0; u < 2; u++) {                                                      \
        const int idx = t + 512 * u;                                                   \
        const int row = idx >> 3;                                                      \
        const int c8  = (idx & 7) << 4;                                                \
        const uint32_t sw = SMEM_SWIZZLE_128B((uint32_t)(row * 128 + c8));             \
        cp_async16(stb + S_BH + sw,                                                    \
                   (const char*)Bw + (size_t)(n0 + row) * rowBb + kb + c8);            \
    }                                                                                  \
    CP_COMMIT();                                                                       \
} while (0)

    const int nch = Kr >> 6;
    #pragma unroll
    for (int p = 0; p < NST; p++) LOAD_CHUNK(p, p);

    float acc[4][4][4];
    #pragma unroll
    for (int mt = 0; mt < 4; mt++)
        #pragma unroll
        for (int nt = 0; nt < 4; nt++)
            #pragma unroll
            for (int r = 0; r < 4; r++) acc[mt][nt][r] = 0.f;

    const int a_row = wm * 64 + (lane & 15);
    const int a_kb  = (lane >> 4) << 4;
    const int b_row = wn * 32 + (lane & 7) + ((lane >> 4) << 3);
    const int b_kb  = ((lane >> 3) & 1) << 4;

    #pragma unroll 1
    for (int c = 0; c < nch; c++) {
        const int st = c % NST;
        if (PASSES == 2) { CP_WAIT1(); } else { CP_WAIT2(); }
        __syncthreads();
        const uint32_t stb = tiles + (uint32_t)st * STAGE;

        #pragma unroll
        for (int ks = 0; ks < 4; ks++) {
            uint32_t ah[4][4], al[4][4];
            #pragma unroll
            for (int mt = 0; mt < 4; mt++) {
                const uint32_t off = SMEM_SWIZZLE_128B(
                    (uint32_t)((a_row + mt * 16) * 128 + ks * 32 + a_kb));
                LDSM_X4(ah[mt], stb + off);
                if (PASSES == 2) LDSM_X4(al[mt], stb + S_AL + off);
            }
            uint32_t bh[2][4];
            #pragma unroll
            for (int nt2 = 0; nt2 < 2; nt2++) {
                const uint32_t off = SMEM_SWIZZLE_128B(
                    (uint32_t)((b_row + nt2 * 16) * 128 + ks * 32 + b_kb));
                LDSM_X4(bh[nt2], stb + S_BH + off);
            }
            #pragma unroll
            for (int mt = 0; mt < 4; mt++)
                #pragma unroll
                for (int nt = 0; nt < 4; nt++)
                    mma_f16(acc[mt][nt], ah[mt],
                            bh[nt >> 1][(nt & 1) * 2], bh[nt >> 1][(nt & 1) * 2 + 1]);
            if (PASSES == 2) {
                #pragma unroll
                for (int mt = 0; mt < 4; mt++)
                    #pragma unroll
                    for (int nt = 0; nt < 4; nt++)
                        mma_f16(acc[mt][nt], al[mt],
                                bh[nt >> 1][(nt & 1) * 2], bh[nt >> 1][(nt & 1) * 2 + 1]);
            }
        }

        __syncthreads();
        if (c + NST < nch) LOAD_CHUNK(c + NST, st);
        else               CP_COMMIT();
    }
#undef LOAD_CHUNK

    // ---------------- epilogue ----------------
    const int qr = lane >> 2;
    const int qc = (lane & 3) << 1;
    #pragma unroll
    for (int mt = 0; mt < 4; mt++) {
        #pragma unroll
        for (int nt = 0; nt < 4; nt++) {
            const int col = n0 + wn * 32 + nt * 8 + qc;
            const float2 bv = *(const float2*)&bias[col];
            #pragma unroll
            for (int half = 0; half < 2; half++) {
                const int row = m0 + wm * 64 + mt * 16 + qr + half * 8;
                float rx = acc[mt][nt][half * 2 + 0] + bv.x;
                float ry = acc[mt][nt][half * 2 + 1] + bv.y;
                if (MODE == MODE_QKV) {
                    rx *= scale; ry *= scale;
                    const int h = col >> 6, d = col & 63;
                    const int bb = row >> 11, ss = row & 2047;
                    const size_t o = ((size_t)(bb * NH + h) * SEQ + ss) * DK + d;
                    *(uint32_t*)&Oh[o] = pack_h16(rx, ry);
                } else if (MODE == MODE_RELU) {
                    rx = fmaxf(rx, 0.f); ry = fmaxf(ry, 0.f);
                    *(uint32_t*)&Oh[(size_t)row * N + col] = pack_h16(rx, ry);
                } else { // MODE_RES
                    float2 rv = *(const float2*)&Res[(size_t)row * N + col];
                    float2 r = make_float2(rx + rv.x, ry + rv.y);
                    *(float2*)&C[(size_t)row * N + col] = r;
                }
            }
        }
    }
}

// ================= tensor-core flash attention (fp16 1-pass) =================
// CTA: 128 queries x 64-key blocks, 8 warps (16 q-rows each).
// S = Qh*Kh ; O += Ph*Vh. Output ctx written split hi/lo (Wo GEMM is 2-pass).
#define SQH  0
#define SKV0 16384
#define KV_STAGE 16384           // kh 0, vh 8192
#define ATTN_SMEM 49152

__global__ __launch_bounds__(256, 2)
void attn_tc(const __half* __restrict__ Qh,
             const __half* __restrict__ Kh, const __half* __restrict__ Vh,
             __half* __restrict__ Actx)   // split A rows, stride 2048
{
    extern __shared__ __align__(1024) char smem[];
    const uint32_t sb = smem_u32(smem);
    const int t = threadIdx.x, lane = t & 31, w = t >> 5;
    const int qt = gridDim.x - 1 - blockIdx.x;
    const int bh = blockIdx.y;
    const int q0 = qt * 128;

    const char* qhB = (const char*)(Qh + ((size_t)bh * SEQ + q0) * DK);
    const char* khB = (const char*)(Kh + (size_t)bh * SEQ * DK);
    const char* vhB = (const char*)(Vh + (size_t)bh * SEQ * DK);

#define LOAD_KV(KB_, ST_) do {                                                   \
    const uint32_t stb = sb + SKV0 + (ST_) * KV_STAGE;                           \
    _Pragma("unroll")                                                            \
    for (int u = 0; u < 2; u++) {                                                \
        const int idx = t + 256 * u;                                             \
        const int row = idx >> 3;                                                \
        const int c8  = (idx & 7) << 4;                                          \
        const uint32_t sw = SMEM_SWIZZLE_128B((uint32_t)(row * 128 + c8));       \
        const size_t go = (size_t)((KB_) * 64 + row) * 128 + c8;                 \
        cp_async16(stb + sw,        khB + go);                                   \
        cp_async16(stb + 8192 + sw, vhB + go);                                   \
    }                                                                            \
} while (0)

    #pragma unroll
    for (int u = 0; u < 4; u++) {
        const int idx = t + 256 * u;
        const int row = idx >> 3;
        const int c8  = (idx & 7) << 4;
        const uint32_t sw = SMEM_SWIZZLE_128B((uint32_t)(row * 128 + c8));
        cp_async16(sb + SQH + sw, qhB + (size_t)row * 128 + c8);
    }
    LOAD_KV(0, 0);
    CP_COMMIT();
    LOAD_KV(1, 1);
    CP_COMMIT();

    const int kbmax = (q0 + 126) >> 6;

    float O[8][4];
    #pragma unroll
    for (int nt = 0; nt < 8; nt++)
        #pragma unroll
        for (int j = 0; j < 4; j++) O[nt][j] = 0.f;
    float m0 = -1e30f, m1 = -1e30f, l0 = 0.f, l1 = 0.f;

    const int a_row = w * 16 + (lane & 15);
    const int a_kb  = (lane >> 4) << 4;
    const int bk_row = (lane & 7) + ((lane >> 4) << 3);
    const int bk_kb  = ((lane >> 3) & 1) << 4;
    const int v_row  = ((lane >> 3) & 1) * 8 + (lane & 7);
    const int v_cb   = (lane >> 4) << 4;

    #pragma unroll 1
    for (int kb = 0; kb <= kbmax; kb++) {
        const int st = kb & 1;
        CP_WAIT1();
        __syncthreads();
        const uint32_t KVB = sb + SKV0 + st * KV_STAGE;

        float sc[8][4];
        #pragma unroll
        for (int nt = 0; nt < 8; nt++)
            #pragma unroll
            for (int j = 0; j < 4; j++) sc[nt][j] = 0.f;

        #pragma unroll
        for (int ks = 0; ks < 4; ks++) {
            uint32_t a[4];
            LDSM_X4(a, sb + SQH + SMEM_SWIZZLE_128B(
                (uint32_t)(a_row * 128 + ks * 32 + a_kb)));
            uint32_t bq[4][4];
            #pragma unroll
            for (int nt2 = 0; nt2 < 4; nt2++)
                LDSM_X4(bq[nt2], KVB + SMEM_SWIZZLE_128B(
                    (uint32_t)((nt2 * 16 + bk_row) * 128 + ks * 32 + bk_kb)));
            #pragma unroll
            for (int nt = 0; nt < 8; nt++)
                mma_f16(sc[nt], a, bq[nt >> 1][(nt & 1) * 2], bq[nt >> 1][(nt & 1) * 2 + 1]);
        }

        if (kb >= 2 * qt) {
            const int cb0  = kb * 64 + 2 * (lane & 3);
            const int row0 = q0 + w * 16 + (lane >> 2);
            #pragma unroll
            for (int nt = 0; nt < 8; nt++) {
                const int cbase = cb0 + nt * 8;
                if (cbase + 0 >= row0)     sc[nt][0] = -1e30f;
                if (cbase + 1 >= row0)     sc[nt][1] = -1e30f;
                if (cbase + 0 >= row0 + 8) sc[nt][2] = -1e30f;
                if (cbase + 1 >= row0 + 8) sc[nt][3] = -1e30f;
            }
        }

        float mx0 = -1e30f, mx1 = -1e30f;
        #pragma unroll
        for (int nt = 0; nt < 8; nt++) {
            mx0 = fmaxf(mx0, fmaxf(sc[nt][0], sc[nt][1]));
            mx1 = fmaxf(mx1, fmaxf(sc[nt][2], sc[nt][3]));
        }
        #pragma unroll
        for (int o = 1; o <= 2; o <<= 1) {
            mx0 = fmaxf(mx0, __shfl_xor_sync(0xffffffffu, mx0, o));
            mx1 = fmaxf(mx1, __shfl_xor_sync(0xffffffffu, mx1, o));
        }
        const float mn0 = fmaxf(m0, mx0), mn1 = fmaxf(m1, mx1);
        const float c0 = __expf(m0 - mn0), c1 = __expf(m1 - mn1);
        m0 = mn0; m1 = mn1;
        float rs0 = 0.f, rs1 = 0.f;
        #pragma unroll
        for (int nt = 0; nt < 8; nt++) {
            sc[nt][0] = __expf(sc[nt][0] - mn0);
            sc[nt][1] = __expf(sc[nt][1] - mn0);
            sc[nt][2] = __expf(sc[nt][2] - mn1);
            sc[nt][3] = __expf(sc[nt][3] - mn1);
            rs0 += sc[nt][0] + sc[nt][1];
            rs1 += sc[nt][2] + sc[nt][3];
        }
        #pragma unroll
        for (int o = 1; o <= 2; o <<= 1) {
            rs0 += __shfl_xor_sync(0xffffffffu, rs0, o);
            rs1 += __shfl_xor_sync(0xffffffffu, rs1, o);
        }
        l0 = l0 * c0 + rs0;
        l1 = l1 * c1 + rs1;
        #pragma unroll
        for (int nt = 0; nt < 8; nt++) {
            O[nt][0] *= c0; O[nt][1] *= c0;
            O[nt][2] *= c1; O[nt][3] *= c1;
        }

        // PV: O += Ph * Vh
        #pragma unroll
        for (int kk = 0; kk < 4; kk++) {
            uint32_t ah[4];
            ah[0] = pack_h16(sc[2*kk][0],   sc[2*kk][1]);
            ah[1] = pack_h16(sc[2*kk][2],   sc[2*kk][3]);
            ah[2] = pack_h16(sc[2*kk+1][0], sc[2*kk+1][1]);
            ah[3] = pack_h16(sc[2*kk+1][2], sc[2*kk+1][3]);
            #pragma unroll
            for (int nt2 = 0; nt2 < 4; nt2++) {
                const uint32_t vaddr = SMEM_SWIZZLE_128B(
                    (uint32_t)((kk * 16 + v_row) * 128 + nt2 * 32 + v_cb));
                uint32_t bv[4];
                LDSM_X4_T(bv, KVB + 8192 + vaddr);
                mma_f16(O[2*nt2],   ah, bv[0], bv[1]);
                mma_f16(O[2*nt2+1], ah, bv[2], bv[3]);
            }
        }

        __syncthreads();
        if (kb + 2 <= kbmax) LOAD_KV(kb + 2, st);
        CP_COMMIT();
    }
#undef LOAD_KV

    // epilogue: write split-A ctx rows (stride 2048) for the 2-pass Wo GEMM
    const int b = bh >> 4, h = bh & 15;
    const int r0 = q0 + w * 16 + (lane >> 2);
    const int dc = 2 * (lane & 3);
    #pragma unroll
    for (int half = 0; half < 2; half++) {
        const int q = r0 + 8 * half;
        const float lv  = (half == 0) ? l0 : l1;
        const float inv = (q == 0) ? 0.f : (1.f / lv);
        const size_t rowb = ((size_t)b * SEQ + q) * 2048;
        #pragma unroll
        for (int nt = 0; nt < 8; nt++) {
            const float x = O[nt][half * 2 + 0] * inv;
            const float y = O[nt][half * 2 + 1] * inv;
            const int col = h * 64 + nt * 8 + dc;
            uint32_t hi, lo;
            split_pack(x, y, hi, lo);
            *(uint32_t*)&Actx[rowb + col]        = hi;
            *(uint32_t*)&Actx[rowb + 1024 + col] = lo;
        }
    }
}

// ---------------- layernorm (optional fp16-hi side output, stride 1024) ----------------
__global__ __launch_bounds__(256)
void ln_kernel(const float* __restrict__ X, const float* __restrict__ G,
               const float* __restrict__ Bt, float* __restrict__ O,
               __half* __restrict__ SP)
{
    __shared__ float ws[8], ws2[8];
    __shared__ float s_mu, s_rs;
    const int t = threadIdx.x;
    const size_t row = blockIdx.x;

    float4 v = *(const float4*)&X[row * D_MODEL + t * 4];
    float s  = v.x + v.y + v.z + v.w;
    float s2 = v.x * v.x + v.y * v.y + v.z * v.z + v.w * v.w;
    #pragma unroll
    for (int o = 16; o; o >>= 1) {
        s  += __shfl_xor_sync(0xffffffffu, s,  o);
        s2 += __shfl_xor_sync(0xffffffffu, s2, o);
    }
    if ((t & 31) == 0) { ws[t >> 5] = s; ws2[t >> 5] = s2; }
    __syncthreads();
    if (t == 0) {
        float S = 0.f, S2 = 0.f;
        #pragma unroll
        for (int w = 0; w < 8; w++) { S += ws[w]; S2 += ws2[w]; }
        const float mu  = S * (1.f / (float)D_MODEL);
        const float var = S2 * (1.f / (float)D_MODEL) - mu * mu;
        s_mu = mu;
        s_rs = rsqrtf(var + 1e-5f);
    }
    __syncthreads();
    const float mu = s_mu, rs = s_rs;

    float4 g = *(const float4*)&G[t * 4];
    float4 b = *(const float4*)&Bt[t * 4];
    float4 r;
    r.x = (v.x - mu) * rs * g.x + b.x;
    r.y = (v.y - mu) * rs * g.y + b.y;
    r.z = (v.z - mu) * rs * g.z + b.z;
    r.w = (v.w - mu) * rs * g.w + b.w;
    *(float4*)&O[row * D_MODEL + t * 4] = r;

    if (SP) {
        const size_t base = row * 1024 + t * 4;
        *(uint2*)&SP[base] = make_uint2(pack_h16(r.x, r.y), pack_h16(r.z, r.w));
    }
}

// ---------------- orchestration ----------------
#define GEMM_SMEM_2P 163840
#define GEMM_SMEM_1P 147456

extern "C" void kernel_launch(void* const* d_in, const int* in_sizes, int n_in,
                              void* d_out, int out_size)
{
    (void)in_sizes; (void)n_in; (void)out_size;

    const float* query = (const float*)d_in[0];
    const float* key_i = (const float*)d_in[1];
    const float* vals  = (const float*)d_in[2];
    const float* Wq = (const float*)d_in[3];
    const float* bq = (const float*)d_in[4];
    const float* Wk = (const float*)d_in[5];
    const float* bk = (const float*)d_in[6];
    const float* Wv = (const float*)d_in[7];
    const float* bv = (const float*)d_in[8];
    const float* Wo = (const float*)d_in[9];
    const float* bo = (const float*)d_in[10];
    const float* ln1g = (const float*)d_in[11];
    const float* ln1b = (const float*)d_in[12];
    const float* W1 = (const float*)d_in[13];
    const float* b1 = (const float*)d_in[14];
    const float* W2 = (const float*)d_in[15];
    const float* b2 = (const float*)d_in[16];
    const float* ln2g = (const float*)d_in[17];
    const float* ln2b = (const float*)d_in[18];
    float* out = (float*)d_out;

    float *pt, *px;
    __half *pqh, *pkh, *pvh, *pab, *phb, *pwb;
    cudaGetSymbolAddress((void**)&pt,  g_t);
    cudaGetSymbolAddress((void**)&px,  g_x);
    cudaGetSymbolAddress((void**)&pqh, g_qh);
    cudaGetSymbolAddress((void**)&pkh, g_kh);
    cudaGetSymbolAddress((void**)&pvh, g_vh);
    cudaGetSymbolAddress((void**)&pab, g_abuf);
    cudaGetSymbolAddress((void**)&phb, g_hbuf);
    cudaGetSymbolAddress((void**)&pwb, g_wbuf);

    cudaFuncSetAttribute(attn_tc,
                         cudaFuncAttributeMaxDynamicSharedMemorySize, ATTN_SMEM);
    cudaFuncSetAttribute(tc_gemm<MODE_QKV, 2>,
                         cudaFuncAttributeMaxDynamicSharedMemorySize, GEMM_SMEM_2P);
    cudaFuncSetAttribute(tc_gemm<MODE_RES, 2>,
                         cudaFuncAttributeMaxDynamicSharedMemorySize, GEMM_SMEM_2P);
    cudaFuncSetAttribute(tc_gemm<MODE_RELU, 1>,
                         cudaFuncAttributeMaxDynamicSharedMemorySize, GEMM_SMEM_1P);
    cudaFuncSetAttribute(tc_gemm<MODE_RES, 1>,
                         cudaFuncAttributeMaxDynamicSharedMemorySize, GEMM_SMEM_1P);

    const dim3 blk(512);
    const dim3 grid_1k(D_MODEL / 128, M_TOT / 256);   // (8, 16)
    const dim3 grid_4k(D_FF / 128,    M_TOT / 256);   // (32, 16)
    const int total4_1k = M_TOT * D_MODEL / 4;

    // ---- QKV projections (2-pass) -> fp16 hi [B,H,S,64] (Q pre-scaled by 1/8) ----
    act_split_kernel<<<(total4_1k + 255) / 256, 256>>>(query, pab, D_MODEL, total4_1k);
    wt_split_kernel<<<dim3(D_MODEL / 32, D_MODEL / 32), 256>>>(Wq, pwb, D_MODEL, D_MODEL);
    tc_gemm<MODE_QKV, 2><<<grid_1k, blk, GEMM_SMEM_2P>>>(pab, pwb, bq, nullptr, nullptr,
                                                         pqh, 0.125f, D_MODEL, D_MODEL);
    act_split_kernel<<<(total4_1k + 255) / 256, 256>>>(key_i, pab, D_MODEL, total4_1k);
    wt_split_kernel<<<dim3(D_MODEL / 32, D_MODEL / 32), 256>>>(Wk, pwb, D_MODEL, D_MODEL);
    tc_gemm<MODE_QKV, 2><<<grid_1k, blk, GEMM_SMEM_2P>>>(pab, pwb, bk, nullptr, nullptr,
                                                         pkh, 1.0f, D_MODEL, D_MODEL);
    act_split_kernel<<<(total4_1k + 255) / 256, 256>>>(vals, pab, D_MODEL, total4_1k);
    wt_split_kernel<<<dim3(D_MODEL / 32, D_MODEL / 32), 256>>>(Wv, pwb, D_MODEL, D_MODEL);
    tc_gemm<MODE_QKV, 2><<<grid_1k, blk, GEMM_SMEM_2P>>>(pab, pwb, bv, nullptr, nullptr,
                                                         pvh, 1.0f, D_MODEL, D_MODEL);

    // ---- 1-pass fp16 causal flash attention -> split ctx in g_abuf ----
    attn_tc<<<dim3(SEQ / 128, NB * NH), dim3(256), ATTN_SMEM>>>(pqh, pkh, pvh, pab);

    // ---- Wo (2-pass) + residual(query) -> g_t ; LN1 -> g_x + hi plane in g_abuf ----
    wt_split_kernel<<<dim3(D_MODEL / 32, D_MODEL / 32), 256>>>(Wo, pwb, D_MODEL, D_MODEL);
    tc_gemm<MODE_RES, 2><<<grid_1k, blk, GEMM_SMEM_2P>>>(pab, pwb, bo, query, pt,
                                                         nullptr, 1.0f, D_MODEL, D_MODEL);
    ln_kernel<<<M_TOT, 256>>>(pt, ln1g, ln1b, px, pab);

    // ---- FFN1 (1-pass): relu(x@W1+b1) -> h hi in g_hbuf ----
    wt_split_kernel<<<dim3(D_MODEL / 32, D_FF / 32), 256>>>(W1, pwb, D_MODEL, D_FF);
    tc_gemm<MODE_RELU, 1><<<grid_4k, blk, GEMM_SMEM_1P>>>(pab, pwb, b1, nullptr, nullptr,
                                                          phb, 1.0f, D_FF, D_MODEL);

    // ---- FFN2 (1-pass) + residual(x) -> g_t ; LN2 -> out ----
    wt_split_kernel<<<dim3(D_FF / 32, D_MODEL / 32), 256>>>(W2, pwb, D_FF, D_MODEL);
    tc_gemm<MODE_RES, 1><<<grid_1k, blk, GEMM_SMEM_1P>>>(phb, pwb, b2, px, pt,
                                                         nullptr, 1.0f, D_MODEL, D_FF);
    ln_kernel<<<M_TOT, 256>>>(pt, ln2g, ln2b, out, nullptr);
}